// round 3
// baseline (speedup 1.0000x reference)
#include <cuda_runtime.h>
#include <math.h>

// ============================ constants ============================
// levels: H = 64,32,16,8,4 ; attention grid 16x16 (q/t = 256)
__constant__ int d_H[5]    = {64, 32, 16, 8, 4};
__constant__ int d_TOFF[5] = {0, 64, 96, 112, 120};

// ============================ scratch ==============================
__device__ float g_fs[655360];       // [img(10)][cin 256][q 256]
__device__ float g_partA[1638400];   // att-conv cin-split partials (2 x 20 x 160 x 256)
__device__ float g_partF[819200];    // feat-conv partials          (2 x 10 x 160 x 256)
__device__ float g_keytT[163840];    // [n][t][k]  (n 20, t 256, k 32)
__device__ float g_valtC[655360];    // [c 128][n 20][t 256]
__device__ float g_kq[81920];        // [img][k 32][q 256]
__device__ float g_final[655360];    // [img][i 256][q 256]  (0-127: 20*vq ; 128-255: vt)
__device__ float g_pT[13107200];     // [img][n][t][q]
__device__ float g_vtpart[1638400];  // [z=kg*10+img][c 128][t 256]
__device__ float g_h[655360];        // [img][oc 256][q 256]
__device__ float g_W2sT[327680];     // [lvl][oc][i]  = combine_w2[oc][i]*bn_scale[lvl][i]
__device__ float g_cbias[1280];      // [lvl][oc]
__device__ float g_wAtt[368640];     // [oc 160][cin 256][9]
__device__ float g_bAtt[160];
__device__ float g_wF[1843200];      // [lvl][oc 160][cin 256][9]
__device__ float g_bF[800];
__device__ int   g_fi0[80], g_fi1[80];
__device__ float g_fw[80];           // downsample H->16 tables, per lvl offset lvl*16
__device__ int   g_ui0[124], g_ui1[124];
__device__ float g_uw[124];          // upsample 16->H tables, per lvl offset d_TOFF

struct FeatPtrs { const float* p[5]; };

// ============================ tables ===============================
__global__ void __launch_bounds__(256) k_tables() {
    int tid = threadIdx.x;
    if (tid < 80) {                       // 16->? no: H -> 16 (fs)
        int lvl = tid >> 4, o = tid & 15;
        int H = d_H[lvl];
        float r = (float)((double)(H - 1) / 15.0);
        float s = (float)o * r;
        int i0 = min((int)floorf(s), H - 1);
        int i1 = min(i0 + 1, H - 1);
        g_fi0[tid] = i0; g_fi1[tid] = i1; g_fw[tid] = s - (float)i0;
    }
    if (tid >= 128 && tid < 252) {        // 16 -> H (upsample)
        int j = tid - 128;
        int lvl = (j < 64) ? 0 : (j < 96) ? 1 : (j < 112) ? 2 : (j < 120) ? 3 : 4;
        int o = j - d_TOFF[lvl];
        int H = d_H[lvl];
        float r = (float)(15.0 / (double)(H - 1));
        float s = (float)o * r;
        int i0 = min((int)floorf(s), 15);
        int i1 = min(i0 + 1, 15);
        g_ui0[j] = i0; g_ui1[j] = i1; g_uw[j] = s - (float)i0;
    }
}

// ===================== weight concat / prep ========================
__global__ void __launch_bounds__(256) k_wcat_att(const float* __restrict__ kw,
                                                  const float* __restrict__ kb,
                                                  const float* __restrict__ vw,
                                                  const float* __restrict__ vb) {
    int idx = blockIdx.x * 256 + threadIdx.x;          // < 368640
    if (idx < 368640) {
        int oc = idx / 2304, r = idx % 2304;
        g_wAtt[idx] = (oc < 32) ? kw[oc * 2304 + r] : vw[(oc - 32) * 2304 + r];
    }
    if (idx < 160) g_bAtt[idx] = (idx < 32) ? kb[idx] : vb[idx - 32];
}

__global__ void __launch_bounds__(256) k_wcat_feat(const float* __restrict__ kw,
                                                   const float* __restrict__ kb,
                                                   const float* __restrict__ vw,
                                                   const float* __restrict__ vb) {
    int idx = blockIdx.x * 256 + threadIdx.x;          // < 1843200
    if (idx < 1843200) {
        int lvl = idx / 368640, r2 = idx % 368640;
        int oc = r2 / 2304, r = r2 % 2304;
        g_wF[idx] = (oc < 32) ? kw[(lvl * 32 + oc) * 2304 + r]
                              : vw[(lvl * 128 + oc - 32) * 2304 + r];
    }
    if (idx < 800) {
        int lvl = idx / 160, oc = idx % 160;
        g_bF[idx] = (oc < 32) ? kb[lvl * 32 + oc] : vb[lvl * 128 + oc - 32];
    }
}

__global__ void __launch_bounds__(256) k_w2s(const float* __restrict__ cw,
                                             const float* __restrict__ gam,
                                             const float* __restrict__ var) {
    int idx = blockIdx.x * 256 + threadIdx.x;          // < 327680
    int lvl = idx >> 16, r = idx & 65535, oc = r >> 8, i = r & 255;
    float sc = gam[lvl * 256 + i] / sqrtf(var[lvl * 256 + i] + 1e-5f);
    g_W2sT[idx] = cw[oc * 512 + 256 + i] * sc;
}

__global__ void __launch_bounds__(256) k_cbias(const float* __restrict__ cw,
                                               const float* __restrict__ cb,
                                               const float* __restrict__ gam,
                                               const float* __restrict__ bet,
                                               const float* __restrict__ mea,
                                               const float* __restrict__ var) {
    int lvl = blockIdx.x, oc = threadIdx.x;
    float s = 0.f;
    for (int i = 0; i < 256; ++i) {
        float sc = gam[lvl * 256 + i] / sqrtf(var[lvl * 256 + i] + 1e-5f);
        s += cw[oc * 512 + 256 + i] * (bet[lvl * 256 + i] - sc * mea[lvl * 256 + i]);
    }
    g_cbias[lvl * 256 + oc] = cb[oc] + s;
}

// ===================== bilinear: feats -> 16x16 ====================
__global__ void __launch_bounds__(256) k_fs(FeatPtrs fp) {
    int idx = blockIdx.x * 256 + threadIdx.x;          // < 655360
    int q = idx & 255, c = (idx >> 8) & 255, img = idx >> 16;
    int lvl = img >> 1, b = img & 1;
    int H = d_H[lvl];
    int y = q >> 4, x = q & 15;
    int t = lvl * 16;
    int y0 = g_fi0[t + y], y1 = g_fi1[t + y];
    int x0 = g_fi0[t + x], x1 = g_fi1[t + x];
    float wy = g_fw[t + y], wx = g_fw[t + x];
    const float* src = fp.p[lvl] + ((size_t)(b * 256 + c)) * H * H;
    float v00 = src[y0 * H + x0], v01 = src[y0 * H + x1];
    float v10 = src[y1 * H + x0], v11 = src[y1 * H + x1];
    float top = v00 * (1.f - wx) + v01 * wx;
    float bot = v10 * (1.f - wx) + v11 * wx;
    g_fs[idx] = top * (1.f - wy) + bot * wy;
}

// ========= 3x3 SAME conv on 16x16, 160 ocs, cin split in 2 =========
// grid (nimg, 10, 2), block 256 (one thread per pixel, 16 ocs per block)
__global__ void __launch_bounds__(256) conv16(const float* __restrict__ in_ext,
                                              int nimg, int perLevel) {
    int img = blockIdx.x, grp = blockIdx.y, cg = blockIdx.z;
    const float* in  = perLevel ? g_fs : in_ext;
    const float* w   = perLevel ? g_wF : g_wAtt;
    float* part      = perLevel ? g_partF : g_partA;
    const float* inp = in + ((size_t)img * 256 + cg * 128) * 256;
    const float* wb  = w + ((size_t)(perLevel ? (img >> 1) : 0) * 160 + grp * 16) * 2304
                         + (size_t)cg * 128 * 9;
    float* outp = part + (((size_t)cg * nimg + img) * 160 + grp * 16) * 256;

    __shared__ float tile[8][18][18];
    __shared__ __align__(16) float wsh[8][9][16];
    int tid = threadIdx.x;
    for (int i = tid; i < 8 * 18 * 18; i += 256) ((float*)tile)[i] = 0.f;

    float4 acc[4];
#pragma unroll
    for (int j = 0; j < 4; ++j) acc[j] = make_float4(0.f, 0.f, 0.f, 0.f);
    int y = tid >> 4, x = tid & 15;

    for (int cc = 0; cc < 128; cc += 8) {
        __syncthreads();
#pragma unroll
        for (int i = 0; i < 8; ++i) {              // 2048 interior elems
            int idx = tid + i * 256;
            int c = idx >> 8, p = idx & 255;
            tile[c][(p >> 4) + 1][(p & 15) + 1] = inp[(cc + c) * 256 + p];
        }
#pragma unroll
        for (int i = 0; i < 5; ++i) {              // 1152 weight elems
            int idx = tid + i * 256;
            if (idx < 1152) {
                int c = idx / 144, r = idx % 144;
                int tap = r / 16, oc = r % 16;
                wsh[c][tap][oc] = wb[(size_t)oc * 2304 + (cc + c) * 9 + tap];
            }
        }
        __syncthreads();
#pragma unroll
        for (int c = 0; c < 8; ++c) {
            float v[9];
#pragma unroll
            for (int dy = 0; dy < 3; ++dy)
#pragma unroll
                for (int dx = 0; dx < 3; ++dx)
                    v[dy * 3 + dx] = tile[c][y + dy][x + dx];
#pragma unroll
            for (int tap = 0; tap < 9; ++tap) {
                float vv = v[tap];
                const float4* wp = (const float4*)&wsh[c][tap][0];
#pragma unroll
                for (int j = 0; j < 4; ++j) {
                    float4 w4 = wp[j];
                    acc[j].x += vv * w4.x; acc[j].y += vv * w4.y;
                    acc[j].z += vv * w4.z; acc[j].w += vv * w4.w;
                }
            }
        }
    }
#pragma unroll
    for (int j = 0; j < 4; ++j) {
        outp[(4 * j + 0) * 256 + tid] = acc[j].x;
        outp[(4 * j + 1) * 256 + tid] = acc[j].y;
        outp[(4 * j + 2) * 256 + tid] = acc[j].z;
        outp[(4 * j + 3) * 256 + tid] = acc[j].w;
    }
}

// ================= partial reductions + layout =====================
__global__ void __launch_bounds__(256) reduce_att() {
    int idx = blockIdx.x * 256 + threadIdx.x;          // < 819200
    int n = idx / 40960, r = idx % 40960;
    int oc = r >> 8, pix = r & 255;
    float s = g_partA[idx] + g_partA[819200 + idx] + g_bAtt[oc];
    if (oc < 32) g_keytT[((size_t)n * 256 + pix) * 32 + oc] = s;
    else         g_valtC[((size_t)(oc - 32) * 20 + n) * 256 + pix] = s;
}

__global__ void __launch_bounds__(256) reduce_feat() {
    int idx = blockIdx.x * 256 + threadIdx.x;          // < 409600
    int img = idx / 40960, r = idx % 40960;
    int oc = r >> 8, pix = r & 255;
    int lvl = img >> 1;
    float s = g_partF[idx] + g_partF[409600 + idx] + g_bF[lvl * 160 + oc];
    if (oc < 32) g_kq[((size_t)img * 32 + oc) * 256 + pix] = s;
    else         g_final[((size_t)img * 256 + (oc - 32)) * 256 + pix] = 20.f * s;
}

// ===================== generic NN GEMM (64x64) =====================
// src 0: logits  A=g_keytT  B=g_kq    C=g_pT
// src 1: h       A=g_W2sT   B=g_final C=g_h
// src 2: part1   A/B/C external; mode=1 epilogue (upsample(h)+cbias)
__global__ void __launch_bounds__(256) gemm_nn(
    const float* __restrict__ Aext, const float* __restrict__ Bext, float* __restrict__ Cext,
    int M, int N, int K, int lda, int ldb, int ldc,
    long long aZ, long long bZ, long long cZ, int aHalf,
    int src, int mode, int lvl, int lgW, int toff) {
    const float* A; const float* B; float* C;
    if (src == 0)      { A = g_keytT; B = g_kq;    C = g_pT; }
    else if (src == 1) { A = g_W2sT;  B = g_final; C = g_h;  }
    else               { A = Aext;    B = Bext;    C = Cext; }
    int z = blockIdx.z;
    A += (size_t)(aHalf ? (z >> 1) : z) * aZ;
    B += (size_t)z * bZ;
    C += (size_t)z * cZ;
    int m0 = blockIdx.x * 64, n0 = blockIdx.y * 64;
    int tid = threadIdx.x, tx = tid & 15, ty = tid >> 4;
    __shared__ float As[8][65];
    __shared__ __align__(16) float Bs[8][64];
    float acc[4][4] = {};

    for (int k0 = 0; k0 < K; k0 += 8) {
        __syncthreads();
#pragma unroll
        for (int e0 = 0; e0 < 2; ++e0) {
            int e = tid + e0 * 256;
            int kk = e & 7, m = e >> 3;
            As[kk][m] = A[(size_t)(m0 + m) * lda + k0 + kk];
        }
#pragma unroll
        for (int e0 = 0; e0 < 2; ++e0) {
            int e = tid + e0 * 256;
            int n = e & 63, kk = e >> 6;
            float bv = 0.f;
            if (n0 + n < N) bv = B[(size_t)(k0 + kk) * ldb + n0 + n];
            Bs[kk][n] = bv;
        }
        __syncthreads();
#pragma unroll
        for (int kk = 0; kk < 8; ++kk) {
            float a[4];
#pragma unroll
            for (int i = 0; i < 4; ++i) a[i] = As[kk][ty * 4 + i];
            float4 b4 = *(const float4*)&Bs[kk][tx * 4];
            float b[4] = {b4.x, b4.y, b4.z, b4.w};
#pragma unroll
            for (int i = 0; i < 4; ++i)
#pragma unroll
                for (int j = 0; j < 4; ++j) acc[i][j] += a[i] * b[j];
        }
    }

    if (mode == 0) {
#pragma unroll
        for (int i = 0; i < 4; ++i) {
            int m = m0 + ty * 4 + i;
#pragma unroll
            for (int j = 0; j < 4; ++j) {
                int n = n0 + tx * 4 + j;
                if (n < N) C[(size_t)m * ldc + n] = acc[i][j];
            }
        }
    } else {
        int img = lvl * 2 + z;
        int Wm = (1 << lgW) - 1;
#pragma unroll
        for (int i = 0; i < 4; ++i) {
            int oc = m0 + ty * 4 + i;
            float cb = g_cbias[lvl * 256 + oc];
            const float* hrow = g_h + ((size_t)img * 256 + oc) * 256;
#pragma unroll
            for (int j = 0; j < 4; ++j) {
                int p = n0 + tx * 4 + j;
                if (p < N) {
                    int yy = p >> lgW, xx = p & Wm;
                    int y0 = g_ui0[toff + yy], y1 = g_ui1[toff + yy];
                    int x0 = g_ui0[toff + xx], x1 = g_ui1[toff + xx];
                    float wy = g_uw[toff + yy], wx = g_uw[toff + xx];
                    float v00 = hrow[y0 * 16 + x0], v01 = hrow[y0 * 16 + x1];
                    float v10 = hrow[y1 * 16 + x0], v11 = hrow[y1 * 16 + x1];
                    float top = v00 * (1.f - wx) + v01 * wx;
                    float bot = v10 * (1.f - wx) + v11 * wx;
                    C[(size_t)oc * ldc + p] = acc[i][j] + top * (1.f - wy) + bot * wy + cb;
                }
            }
        }
    }
}

// ===================== softmax over q (row = img,n,t) ==============
__global__ void __launch_bounds__(256) softmax_k() {
    int w = threadIdx.x >> 5, lane = threadIdx.x & 31;
    size_t r = (size_t)blockIdx.x * 8 + w;            // < 51200
    float* row = g_pT + r * 256;
    float v[8];
    float mx = -1e30f;
#pragma unroll
    for (int i = 0; i < 8; ++i) { v[i] = row[lane + i * 32]; mx = fmaxf(mx, v[i]); }
#pragma unroll
    for (int o = 16; o > 0; o >>= 1) mx = fmaxf(mx, __shfl_xor_sync(0xffffffffu, mx, o));
    float s = 0.f;
#pragma unroll
    for (int i = 0; i < 8; ++i) { v[i] = __expf(v[i] - mx); s += v[i]; }
#pragma unroll
    for (int o = 16; o > 0; o >>= 1) s += __shfl_xor_sync(0xffffffffu, s, o);
    float inv = 1.f / s;
#pragma unroll
    for (int i = 0; i < 8; ++i) row[lane + i * 32] = v[i] * inv;
}

// ============ vt NT GEMM, split-K over class groups ================
// grid (2, 4, 50): z = kg*10+img ; C[c][t] partials
__global__ void __launch_bounds__(256) gemm_vt() {
    int z = blockIdx.z, img = z % 10, kg = z / 10;
    const float* A = g_valtC;                          // [c][k], lda 5120
    const float* Bb = g_pT + (size_t)img * 1310720;
    float* C = g_vtpart + (size_t)z * 32768;
    int m0 = blockIdx.x * 64, t0 = blockIdx.y * 64;
    int tid = threadIdx.x, tx = tid & 15, ty = tid >> 4;
    __shared__ float As[8][65], Bs[8][65];
    float acc[4][4] = {};
    int kb = kg * 1024;
    for (int k0 = kb; k0 < kb + 1024; k0 += 8) {
        __syncthreads();
        const float* Bq = Bb + (size_t)(k0 >> 8) * 65536 + (k0 & 255);
#pragma unroll
        for (int e0 = 0; e0 < 2; ++e0) {
            int e = tid + e0 * 256;
            int kk = e & 7, m = e >> 3;
            As[kk][m] = A[(size_t)(m0 + m) * 5120 + k0 + kk];
            Bs[kk][m] = Bq[(size_t)(t0 + m) * 256 + kk];
        }
        __syncthreads();
#pragma unroll
        for (int kk = 0; kk < 8; ++kk) {
            float a[4], b[4];
#pragma unroll
            for (int i = 0; i < 4; ++i) a[i] = As[kk][ty * 4 + i];
#pragma unroll
            for (int j = 0; j < 4; ++j) b[j] = Bs[kk][tx * 4 + j];
#pragma unroll
            for (int i = 0; i < 4; ++i)
#pragma unroll
                for (int j = 0; j < 4; ++j) acc[i][j] += a[i] * b[j];
        }
    }
#pragma unroll
    for (int i = 0; i < 4; ++i)
#pragma unroll
        for (int j = 0; j < 4; ++j)
            C[(size_t)(m0 + ty * 4 + i) * 256 + t0 + tx * 4 + j] = acc[i][j];
}

__global__ void __launch_bounds__(256) vt_reduce() {
    int idx = blockIdx.x * 256 + threadIdx.x;          // < 327680
    int img = idx >> 15, r = idx & 32767;
    float s = 0.f;
#pragma unroll
    for (int kg = 0; kg < 5; ++kg) s += g_vtpart[((size_t)(kg * 10 + img) << 15) + r];
    int c = r >> 8, t = r & 255;
    g_final[((size_t)img * 256 + 128 + c) * 256 + t] = s;
}

// ===================== attention upsample ==========================
// grid (256 t, 40 bn) per level
__global__ void __launch_bounds__(256) attn_k(float* __restrict__ out,
                                              int lvl, int lg, int toff) {
    int H = 1 << lg;
    int t = blockIdx.x, bn = blockIdx.y;
    int b = bn / 20, n = bn - b * 20;
    int img = lvl * 2 + b;
    const float* row = g_pT + ((size_t)((img * 20 + n) * 256 + t)) * 256;
    __shared__ float sr[256];
    __shared__ int sy0[64], sy1[64];
    __shared__ float swy[64];
    int tid = threadIdx.x;
    sr[tid] = row[tid];
    if (tid < H) { sy0[tid] = g_ui0[toff + tid]; sy1[tid] = g_ui1[toff + tid]; swy[tid] = g_uw[toff + tid]; }
    __syncthreads();
    float* ob = out + ((size_t)bn * 256 + t) * H * H;
    for (int p = tid; p < H * H; p += 256) {
        int y = p >> lg, x = p & (H - 1);
        int y0 = sy0[y], y1 = sy1[y];
        int x0 = sy0[x], x1 = sy1[x];
        float wy = swy[y], wx = swy[x];
        float v00 = sr[y0 * 16 + x0], v01 = sr[y0 * 16 + x1];
        float v10 = sr[y1 * 16 + x0], v11 = sr[y1 * 16 + x1];
        float top = v00 * (1.f - wx) + v01 * wx;
        float bot = v10 * (1.f - wx) + v11 * wx;
        ob[p] = top * (1.f - wy) + bot * wy;
    }
}

// ============================ launch ===============================
extern "C" void kernel_launch(void* const* d_in, const int* in_sizes, int n_in,
                              void* d_out, int out_size) {
    const float* feat[5];
    for (int i = 0; i < 5; ++i) feat[i] = (const float*)d_in[i];
    const float* att   = (const float*)d_in[5];
    const float* ktw   = (const float*)d_in[6];
    const float* ktb   = (const float*)d_in[7];
    const float* vtw   = (const float*)d_in[8];
    const float* vtb   = (const float*)d_in[9];
    const float* kqw   = (const float*)d_in[10];
    const float* kqb   = (const float*)d_in[11];
    const float* vqw   = (const float*)d_in[12];
    const float* vqb   = (const float*)d_in[13];
    const float* bng   = (const float*)d_in[14];
    const float* bnb   = (const float*)d_in[15];
    const float* bnm   = (const float*)d_in[16];
    const float* bnv   = (const float*)d_in[17];
    const float* cw    = (const float*)d_in[18];
    const float* cb    = (const float*)d_in[19];
    float* out = (float*)d_out;

    static const int HWs[5]    = {4096, 1024, 256, 64, 16};
    static const int lg[5]     = {6, 5, 4, 3, 2};
    static const int toff[5]   = {0, 64, 96, 112, 120};
    static const int outoff[5] = {0, 2097152, 2621440, 2752512, 2785280};
    static const int attoff[5] = {2793472, 44736512, 55222272, 57843712, 58499072};

    FeatPtrs fp;
    for (int i = 0; i < 5; ++i) fp.p[i] = feat[i];

    k_tables<<<1, 256>>>();
    k_wcat_att<<<1440, 256>>>(ktw, ktb, vtw, vtb);
    k_wcat_feat<<<7200, 256>>>(kqw, kqb, vqw, vqb);
    k_w2s<<<1280, 256>>>(cw, bng, bnv);
    k_cbias<<<5, 256>>>(cw, cb, bng, bnb, bnm, bnv);
    k_fs<<<2560, 256>>>(fp);

    conv16<<<dim3(20, 10, 2), 256>>>(att, 20, 0);
    conv16<<<dim3(10, 10, 2), 256>>>(nullptr, 10, 1);
    reduce_att<<<3200, 256>>>();
    reduce_feat<<<1600, 256>>>();

    // logits: C[(n,t)][q] per img
    gemm_nn<<<dim3(80, 4, 10), 256>>>(nullptr, nullptr, nullptr,
        5120, 256, 32, 32, 256, 256,
        0LL, 8192LL, 1310720LL, 0, /*src*/0, /*mode*/0, 0, 0, 0);

    softmax_k<<<6400, 256>>>();

    gemm_vt<<<dim3(2, 4, 50), 256>>>();
    vt_reduce<<<1280, 256>>>();

    // h: C[oc][q] per img
    gemm_nn<<<dim3(4, 4, 10), 256>>>(nullptr, nullptr, nullptr,
        256, 256, 256, 256, 256, 256,
        65536LL, 65536LL, 65536LL, 1, /*src*/1, /*mode*/0, 0, 0, 0);

    // outs: per level, C[oc][p] = W1*feat + upsample(h) + cbias
    for (int l = 0; l < 5; ++l) {
        int HW = HWs[l];
        gemm_nn<<<dim3(4, (HW + 63) / 64, 2), 256>>>(
            cw, feat[l], out + outoff[l],
            256, HW, 256, 512, HW, HW,
            0LL, (long long)256 * HW, (long long)256 * HW, 0,
            /*src*/2, /*mode*/1, l, lg[l], toff[l]);
    }

    // attns: per level
    for (int l = 0; l < 5; ++l)
        attn_k<<<dim3(256, 40), 256>>>(out + attoff[l], l, lg[l], toff[l]);
}

// round 4
// speedup vs baseline: 1.1905x; 1.1905x over previous
#include <cuda_runtime.h>
#include <math.h>

// ============================ constants ============================
__constant__ int d_H[5]    = {64, 32, 16, 8, 4};
__constant__ int d_TOFF[5] = {0, 64, 96, 112, 120};

// ============================ scratch ==============================
__device__ float g_fs[655360];        // [fi(10)][cin 256][q 256]
__device__ float g_part[2457600];     // conv partials [cg 2][img 30][oc 160][pix 256]
__device__ float g_keytT[163840];     // [n][t][k]  (n 20, t 256, k 32)
__device__ float g_valtC[655360];     // [c 128][n 20][t 256]  -> [c][k 5120]
__device__ float g_kq[81920];         // [fi][k 32][q 256]
__device__ float g_final[655360];     // [fi][i 256][q 256]  (0-127: 20*vq ; 128-255: vt)
__device__ float g_pT[13107200];      // [fi][n][t][q]
__device__ float g_vtpart[3276800];   // [z=kg*10+fi][c 128][t 256]
__device__ float g_h[655360];         // [fi][oc 256][q 256]
__device__ float g_W2sT[327680];      // [lvl][oc][i]
__device__ float g_cbias[1280];       // [lvl][oc]
__device__ float g_wAtt[368640];      // [oc 160][cin 256][9]
__device__ float g_bAtt[160];
__device__ float g_wF[1843200];       // [lvl][oc 160][cin 256][9]
__device__ float g_bF[800];
__device__ int   g_fi0[80], g_fi1[80];
__device__ float g_fw[80];            // H->16 tables (per lvl offset lvl*16)
__device__ int   g_ui0[124], g_ui1[124];
__device__ float g_uw[124];           // 16->H tables (per lvl offset d_TOFF)

struct FeatPtrs { const float* p[5]; };

// ============================ tables ===============================
__global__ void __launch_bounds__(256) k_tables() {
    int tid = threadIdx.x;
    if (tid < 80) {                       // H -> 16 (fs downsample)
        int lvl = tid >> 4, o = tid & 15;
        int H = d_H[lvl];
        float r = (float)((double)(H - 1) / 15.0);
        float s = (float)o * r;
        int i0 = min((int)floorf(s), H - 1);
        int i1 = min(i0 + 1, H - 1);
        g_fi0[tid] = i0; g_fi1[tid] = i1; g_fw[tid] = s - (float)i0;
    }
    if (tid >= 128 && tid < 252) {        // 16 -> H (upsample)
        int j = tid - 128;
        int lvl = (j < 64) ? 0 : (j < 96) ? 1 : (j < 112) ? 2 : (j < 120) ? 3 : 4;
        int o = j - d_TOFF[lvl];
        int H = d_H[lvl];
        float r = (float)(15.0 / (double)(H - 1));
        float s = (float)o * r;
        int i0 = min((int)floorf(s), 15);
        int i1 = min(i0 + 1, 15);
        g_ui0[j] = i0; g_ui1[j] = i1; g_uw[j] = s - (float)i0;
    }
}

// ===================== weight concat / prep ========================
__global__ void __launch_bounds__(256) k_wcat_att(const float* __restrict__ kw,
                                                  const float* __restrict__ kb,
                                                  const float* __restrict__ vw,
                                                  const float* __restrict__ vb) {
    int idx = blockIdx.x * 256 + threadIdx.x;
    if (idx < 368640) {
        int oc = idx / 2304, r = idx % 2304;
        g_wAtt[idx] = (oc < 32) ? kw[oc * 2304 + r] : vw[(oc - 32) * 2304 + r];
    }
    if (idx < 160) g_bAtt[idx] = (idx < 32) ? kb[idx] : vb[idx - 32];
}

__global__ void __launch_bounds__(256) k_wcat_feat(const float* __restrict__ kw,
                                                   const float* __restrict__ kb,
                                                   const float* __restrict__ vw,
                                                   const float* __restrict__ vb) {
    int idx = blockIdx.x * 256 + threadIdx.x;
    if (idx < 1843200) {
        int lvl = idx / 368640, r2 = idx % 368640;
        int oc = r2 / 2304, r = r2 % 2304;
        g_wF[idx] = (oc < 32) ? kw[(lvl * 32 + oc) * 2304 + r]
                              : vw[(lvl * 128 + oc - 32) * 2304 + r];
    }
    if (idx < 800) {
        int lvl = idx / 160, oc = idx % 160;
        g_bF[idx] = (oc < 32) ? kb[lvl * 32 + oc] : vb[lvl * 128 + oc - 32];
    }
}

__global__ void __launch_bounds__(256) k_w2s(const float* __restrict__ cw,
                                             const float* __restrict__ gam,
                                             const float* __restrict__ var) {
    int idx = blockIdx.x * 256 + threadIdx.x;          // < 327680
    int lvl = idx >> 16, r = idx & 65535, oc = r >> 8, i = r & 255;
    float sc = gam[lvl * 256 + i] / sqrtf(var[lvl * 256 + i] + 1e-5f);
    g_W2sT[idx] = cw[oc * 512 + 256 + i] * sc;
}

__global__ void __launch_bounds__(256) k_cbias(const float* __restrict__ cw,
                                               const float* __restrict__ cb,
                                               const float* __restrict__ gam,
                                               const float* __restrict__ bet,
                                               const float* __restrict__ mea,
                                               const float* __restrict__ var) {
    int lvl = blockIdx.x, oc = threadIdx.x;
    float s = 0.f;
    for (int i = 0; i < 256; ++i) {
        float sc = gam[lvl * 256 + i] / sqrtf(var[lvl * 256 + i] + 1e-5f);
        s += cw[oc * 512 + 256 + i] * (bet[lvl * 256 + i] - sc * mea[lvl * 256 + i]);
    }
    g_cbias[lvl * 256 + oc] = cb[oc] + s;
}

// ===================== bilinear: feats -> 16x16 ====================
__global__ void __launch_bounds__(256) k_fs(FeatPtrs fp) {
    int idx = blockIdx.x * 256 + threadIdx.x;          // < 655360
    int q = idx & 255, c = (idx >> 8) & 255, img = idx >> 16;
    int lvl = img >> 1, b = img & 1;
    int H = d_H[lvl];
    int y = q >> 4, x = q & 15;
    int t = lvl * 16;
    int y0 = g_fi0[t + y], y1 = g_fi1[t + y];
    int x0 = g_fi0[t + x], x1 = g_fi1[t + x];
    float wy = g_fw[t + y], wx = g_fw[t + x];
    const float* src = fp.p[lvl] + ((size_t)(b * 256 + c)) * H * H;
    float v00 = src[y0 * H + x0], v01 = src[y0 * H + x1];
    float v10 = src[y1 * H + x0], v11 = src[y1 * H + x1];
    float top = v00 * (1.f - wx) + v01 * wx;
    float bot = v10 * (1.f - wx) + v11 * wx;
    g_fs[idx] = top * (1.f - wy) + bot * wy;
}

// ===== 3x3 SAME conv on 16x16, merged att(20 imgs)+feat(10 imgs) ===
// grid (30, 10, 2): x=img (0..19 att, 20..29 feat), y=16-oc group, z=128-cin group
__global__ void __launch_bounds__(256) conv16(const float* __restrict__ att) {
    int img = blockIdx.x, grp = blockIdx.y, cg = blockIdx.z;
    const float* inp; const float* wb;
    if (img < 20) {
        inp = att + (size_t)img * 65536 + (size_t)cg * 32768;
        wb  = g_wAtt + (size_t)grp * 16 * 2304 + (size_t)cg * 1152;
    } else {
        int fi = img - 20;
        inp = g_fs + (size_t)fi * 65536 + (size_t)cg * 32768;
        wb  = g_wF + (size_t)(fi >> 1) * 368640 + (size_t)grp * 16 * 2304 + (size_t)cg * 1152;
    }
    float* outp = g_part + (((size_t)cg * 30 + img) * 160 + grp * 16) * 256;

    __shared__ float tile[8][18][18];
    __shared__ __align__(16) float wsh[8][9][16];
    int tid = threadIdx.x;
    for (int i = tid; i < 8 * 18 * 18; i += 256) ((float*)tile)[i] = 0.f;

    float4 acc[4];
#pragma unroll
    for (int j = 0; j < 4; ++j) acc[j] = make_float4(0.f, 0.f, 0.f, 0.f);
    int y = tid >> 4, x = tid & 15;

    for (int cc = 0; cc < 128; cc += 8) {
        __syncthreads();
#pragma unroll
        for (int i = 0; i < 8; ++i) {
            int idx = tid + i * 256;
            int c = idx >> 8, p = idx & 255;
            tile[c][(p >> 4) + 1][(p & 15) + 1] = inp[(cc + c) * 256 + p];
        }
#pragma unroll
        for (int i = 0; i < 5; ++i) {
            int idx = tid + i * 256;
            if (idx < 1152) {
                int c = idx / 144, r = idx % 144;
                int tap = r / 16, oc = r % 16;
                wsh[c][tap][oc] = wb[(size_t)oc * 2304 + (cc + c) * 9 + tap];
            }
        }
        __syncthreads();
#pragma unroll
        for (int c = 0; c < 8; ++c) {
            float v[9];
#pragma unroll
            for (int dy = 0; dy < 3; ++dy)
#pragma unroll
                for (int dx = 0; dx < 3; ++dx)
                    v[dy * 3 + dx] = tile[c][y + dy][x + dx];
#pragma unroll
            for (int tap = 0; tap < 9; ++tap) {
                float vv = v[tap];
                const float4* wp = (const float4*)&wsh[c][tap][0];
#pragma unroll
                for (int j = 0; j < 4; ++j) {
                    float4 w4 = wp[j];
                    acc[j].x += vv * w4.x; acc[j].y += vv * w4.y;
                    acc[j].z += vv * w4.z; acc[j].w += vv * w4.w;
                }
            }
        }
    }
#pragma unroll
    for (int j = 0; j < 4; ++j) {
        outp[(4 * j + 0) * 256 + tid] = acc[j].x;
        outp[(4 * j + 1) * 256 + tid] = acc[j].y;
        outp[(4 * j + 2) * 256 + tid] = acc[j].z;
        outp[(4 * j + 3) * 256 + tid] = acc[j].w;
    }
}

// ================ merged partial reduction + layout ================
__global__ void __launch_bounds__(256) reduce_all() {
    int idx = blockIdx.x * 256 + threadIdx.x;          // < 1228800
    int img = idx / 40960, r = idx % 40960;
    int oc = r >> 8, pix = r & 255;
    float s = g_part[idx] + g_part[1228800 + idx];
    if (img < 20) {
        s += g_bAtt[oc];
        if (oc < 32) g_keytT[((size_t)img * 256 + pix) * 32 + oc] = s;
        else         g_valtC[((size_t)(oc - 32) * 20 + img) * 256 + pix] = s;
    } else {
        int fi = img - 20, lvl = fi >> 1;
        s += g_bF[lvl * 160 + oc];
        if (oc < 32) g_kq[((size_t)fi * 32 + oc) * 256 + pix] = s;
        else         g_final[((size_t)fi * 256 + (oc - 32)) * 256 + pix] = 20.f * s;
    }
}

// =============== 128x64 micro-kernel helper macro ==================
#define FMA4(AC, AS) { AC.x += (AS) * b.x; AC.y += (AS) * b.y; AC.z += (AS) * b.z; AC.w += (AS) * b.w; }

// ============ logits: pT[n,t][q] = keytT[n,t][k] * kq[k][q] ========
// grid (40, 4, 10): m0=bx*128 over nt, q0=by*64, z=fi. K=32, single tile.
__global__ void __launch_bounds__(256) k_logits() {
    int m0 = blockIdx.x * 128, q0 = blockIdx.y * 64;
    int fi = blockIdx.z;
    const float* B = g_kq + (size_t)fi * 8192;
    float* C = g_pT + (size_t)fi * 1310720;
    __shared__ float As[32][136];
    __shared__ __align__(16) float Bs[32][64];
    int tid = threadIdx.x, tx = tid & 15, ty = tid >> 4;

#pragma unroll
    for (int i = 0; i < 4; ++i) {                       // A: 128x32
        int u = tid + i * 256;
        int rr = u >> 3, ko = (u & 7) * 4;
        float4 av = *(const float4*)&g_keytT[(size_t)(m0 + rr) * 32 + ko];
        As[ko + 0][rr] = av.x; As[ko + 1][rr] = av.y;
        As[ko + 2][rr] = av.z; As[ko + 3][rr] = av.w;
    }
#pragma unroll
    for (int i = 0; i < 8; ++i) {                       // B: 32x64
        int e = tid + i * 256;
        int n = e & 63, kk = e >> 6;
        Bs[kk][n] = B[(size_t)kk * 256 + q0 + n];
    }
    __syncthreads();

    float4 acc[8];
#pragma unroll
    for (int i = 0; i < 8; ++i) acc[i] = make_float4(0.f, 0.f, 0.f, 0.f);
#pragma unroll
    for (int kk = 0; kk < 32; ++kk) {
        float4 a0 = *(const float4*)&As[kk][ty * 8];
        float4 a1 = *(const float4*)&As[kk][ty * 8 + 4];
        float4 b  = *(const float4*)&Bs[kk][tx * 4];
        FMA4(acc[0], a0.x) FMA4(acc[1], a0.y) FMA4(acc[2], a0.z) FMA4(acc[3], a0.w)
        FMA4(acc[4], a1.x) FMA4(acc[5], a1.y) FMA4(acc[6], a1.z) FMA4(acc[7], a1.w)
    }
#pragma unroll
    for (int i = 0; i < 8; ++i)
        *(float4*)&C[(size_t)(m0 + ty * 8 + i) * 256 + q0 + tx * 4] = acc[i];
}

// ===================== softmax over q ==============================
__global__ void __launch_bounds__(256) softmax_k() {
    int w = threadIdx.x >> 5, lane = threadIdx.x & 31;
    size_t r = (size_t)blockIdx.x * 8 + w;              // < 51200
    float* row = g_pT + r * 256;
    float v[8];
    float mx = -1e30f;
#pragma unroll
    for (int i = 0; i < 8; ++i) { v[i] = row[lane + i * 32]; mx = fmaxf(mx, v[i]); }
#pragma unroll
    for (int o = 16; o > 0; o >>= 1) mx = fmaxf(mx, __shfl_xor_sync(0xffffffffu, mx, o));
    float s = 0.f;
#pragma unroll
    for (int i = 0; i < 8; ++i) { v[i] = __expf(v[i] - mx); s += v[i]; }
#pragma unroll
    for (int o = 16; o > 0; o >>= 1) s += __shfl_xor_sync(0xffffffffu, s, o);
    float inv = 1.f / s;
#pragma unroll
    for (int i = 0; i < 8; ++i) row[lane + i * 32] = v[i] * inv;
}

// ====== vt: C[c][t] += valtC[c][k] * pT[n(k)][t][a(k)], splitK=10 ==
// grid (4, 100): t0=bx*64, by = kg*10+fi
__global__ void __launch_bounds__(256) k_vt() {
    int t0 = blockIdx.x * 64;
    int z = blockIdx.y, fi = z % 10, kg = z / 10;
    const float* Bp = g_pT + (size_t)fi * 1310720;
    float* Cp = g_vtpart + (size_t)z * 32768;
    __shared__ float As[16][136];
    __shared__ __align__(16) float Bs[16][64];
    int tid = threadIdx.x, tx = tid & 15, ty = tid >> 4;
    float4 acc[8];
#pragma unroll
    for (int i = 0; i < 8; ++i) acc[i] = make_float4(0.f, 0.f, 0.f, 0.f);

    int kbase = kg * 512;
    for (int k0 = kbase; k0 < kbase + 512; k0 += 16) {
        int nblk = k0 >> 8, a0 = k0 & 255;
        __syncthreads();
        {
            int rr = tid >> 1;
#pragma unroll
            for (int e0 = 0; e0 < 2; ++e0) {
                int ko = (tid & 1) * 4 + e0 * 8;
                float4 av = *(const float4*)&g_valtC[(size_t)rr * 5120 + k0 + ko];
                As[ko + 0][rr] = av.x; As[ko + 1][rr] = av.y;
                As[ko + 2][rr] = av.z; As[ko + 3][rr] = av.w;
            }
        }
        const float* Bn = Bp + (size_t)nblk * 65536 + a0;
#pragma unroll
        for (int e0 = 0; e0 < 4; ++e0) {
            int e = tid + e0 * 256;
            int tt = e >> 4, kk = e & 15;
            Bs[kk][tt] = Bn[(size_t)(t0 + tt) * 256 + kk];
        }
        __syncthreads();
#pragma unroll
        for (int kk = 0; kk < 16; ++kk) {
            float4 a0v = *(const float4*)&As[kk][ty * 8];
            float4 a1v = *(const float4*)&As[kk][ty * 8 + 4];
            float4 b   = *(const float4*)&Bs[kk][tx * 4];
            FMA4(acc[0], a0v.x) FMA4(acc[1], a0v.y) FMA4(acc[2], a0v.z) FMA4(acc[3], a0v.w)
            FMA4(acc[4], a1v.x) FMA4(acc[5], a1v.y) FMA4(acc[6], a1v.z) FMA4(acc[7], a1v.w)
        }
    }
#pragma unroll
    for (int i = 0; i < 8; ++i)
        *(float4*)&Cp[(size_t)(ty * 8 + i) * 256 + t0 + tx * 4] = acc[i];
}

__global__ void __launch_bounds__(256) vt_reduce() {
    int idx = blockIdx.x * 256 + threadIdx.x;          // < 327680
    int fi = idx >> 15, r = idx & 32767;
    float s = 0.f;
#pragma unroll
    for (int kg = 0; kg < 10; ++kg) s += g_vtpart[((size_t)(kg * 10 + fi) << 15) + r];
    int c = r >> 8, t = r & 255;
    g_final[((size_t)fi * 256 + 128 + c) * 256 + t] = s;
}

// ============ h = W2sT * final (64x64 tile, micro 4x4) =============
__global__ void __launch_bounds__(256) k_h() {
    int z = blockIdx.z;
    const float* A = g_W2sT + (size_t)(z >> 1) * 65536;
    const float* B = g_final + (size_t)z * 65536;
    float* C = g_h + (size_t)z * 65536;
    int m0 = blockIdx.x * 64, n0 = blockIdx.y * 64;
    int tid = threadIdx.x, tx = tid & 15, ty = tid >> 4;
    __shared__ float As[8][65];
    __shared__ __align__(16) float Bs[8][64];
    float acc[4][4] = {};
    for (int k0 = 0; k0 < 256; k0 += 8) {
        __syncthreads();
#pragma unroll
        for (int e0 = 0; e0 < 2; ++e0) {
            int e = tid + e0 * 256;
            int kk = e & 7, m = e >> 3;
            As[kk][m] = A[(size_t)(m0 + m) * 256 + k0 + kk];
        }
#pragma unroll
        for (int e0 = 0; e0 < 2; ++e0) {
            int e = tid + e0 * 256;
            int n = e & 63, kk = e >> 6;
            Bs[kk][n] = B[(size_t)(k0 + kk) * 256 + n0 + n];
        }
        __syncthreads();
#pragma unroll
        for (int kk = 0; kk < 8; ++kk) {
            float a[4];
#pragma unroll
            for (int i = 0; i < 4; ++i) a[i] = As[kk][ty * 4 + i];
            float4 b4 = *(const float4*)&Bs[kk][tx * 4];
            float b[4] = {b4.x, b4.y, b4.z, b4.w};
#pragma unroll
            for (int i = 0; i < 4; ++i)
#pragma unroll
                for (int j = 0; j < 4; ++j) acc[i][j] += a[i] * b[j];
        }
    }
#pragma unroll
    for (int i = 0; i < 4; ++i)
#pragma unroll
        for (int j = 0; j < 4; ++j)
            C[(size_t)(m0 + ty * 4 + i) * 256 + n0 + tx * 4 + j] = acc[i][j];
}

// == part1: out[oc][p] = W1*feat + upsample16(h) + cbias (128x64) ===
// grid (2, nT, 2): m0=bx*128, n0=by*64, b=bz
__global__ void __launch_bounds__(256) k_part1(const float* __restrict__ cw,
                                               const float* __restrict__ feat,
                                               float* __restrict__ out,
                                               int N, int lvl, int lgW, int toff) {
    int m0 = blockIdx.x * 128, n0 = blockIdx.y * 64, b = blockIdx.z;
    const float* Bb = feat + (size_t)b * 256 * N;
    float* Cb = out + (size_t)b * 256 * N;
    int img = lvl * 2 + b;
    __shared__ float As[16][136];
    __shared__ __align__(16) float Bs[16][64];
    int tid = threadIdx.x, tx = tid & 15, ty = tid >> 4;
    float4 acc[8];
#pragma unroll
    for (int i = 0; i < 8; ++i) acc[i] = make_float4(0.f, 0.f, 0.f, 0.f);

    for (int k0 = 0; k0 < 256; k0 += 16) {
        __syncthreads();
        {
            int rr = tid >> 1;
#pragma unroll
            for (int e0 = 0; e0 < 2; ++e0) {
                int ko = (tid & 1) * 4 + e0 * 8;
                float4 av = *(const float4*)&cw[(size_t)(m0 + rr) * 512 + k0 + ko];
                As[ko + 0][rr] = av.x; As[ko + 1][rr] = av.y;
                As[ko + 2][rr] = av.z; As[ko + 3][rr] = av.w;
            }
        }
#pragma unroll
        for (int e0 = 0; e0 < 4; ++e0) {
            int e = tid + e0 * 256;
            int n = e & 63, kk = e >> 4;
            // note: layout [kk][n] with kk = e>>4 requires n = e&15? use n-major:
            n = e & 63; kk = e >> 6;                     // kk 0..15 over 4 e0s
            float bv = 0.f;
            int nn = n0 + n;
            if (nn < N) bv = Bb[(size_t)(k0 + kk) * N + nn];
            Bs[kk][n] = bv;
        }
        __syncthreads();
#pragma unroll
        for (int kk = 0; kk < 16; ++kk) {
            float4 a0v = *(const float4*)&As[kk][ty * 8];
            float4 a1v = *(const float4*)&As[kk][ty * 8 + 4];
            float4 b   = *(const float4*)&Bs[kk][tx * 4];
            FMA4(acc[0], a0v.x) FMA4(acc[1], a0v.y) FMA4(acc[2], a0v.z) FMA4(acc[3], a0v.w)
            FMA4(acc[4], a1v.x) FMA4(acc[5], a1v.y) FMA4(acc[6], a1v.z) FMA4(acc[7], a1v.w)
        }
    }

    int Wm = (1 << lgW) - 1;
#pragma unroll
    for (int i = 0; i < 8; ++i) {
        int oc = m0 + ty * 8 + i;
        float cbv = g_cbias[lvl * 256 + oc];
        const float* hrow = g_h + ((size_t)img * 256 + oc) * 256;
        float av[4] = {acc[i].x, acc[i].y, acc[i].z, acc[i].w};
#pragma unroll
        for (int j = 0; j < 4; ++j) {
            int p = n0 + tx * 4 + j;
            if (p < N) {
                int yy = p >> lgW, xx = p & Wm;
                int y0 = g_ui0[toff + yy], y1 = g_ui1[toff + yy];
                int x0 = g_ui0[toff + xx], x1 = g_ui1[toff + xx];
                float wy = g_uw[toff + yy], wx = g_uw[toff + xx];
                float v00 = hrow[y0 * 16 + x0], v01 = hrow[y0 * 16 + x1];
                float v10 = hrow[y1 * 16 + x0], v11 = hrow[y1 * 16 + x1];
                float top = v00 * (1.f - wx) + v01 * wx;
                float bot = v10 * (1.f - wx) + v11 * wx;
                Cb[(size_t)oc * N + p] = av[j] + top * (1.f - wy) + bot * wy + cbv;
            }
        }
    }
}

// ===================== attention upsample (float4) =================
// grid (256 t, 40 bn) per level
__global__ void __launch_bounds__(256) attn_k(float* __restrict__ out,
                                              int lvl, int lg, int toff) {
    int H = 1 << lg;
    int t = blockIdx.x, bn = blockIdx.y;
    int b = bn / 20, n = bn - b * 20;
    int img = lvl * 2 + b;
    const float* row = g_pT + ((size_t)((img * 20 + n) * 256 + t)) * 256;
    __shared__ float sr[256];
    __shared__ int sy0[64], sy1[64];
    __shared__ float swy[64];
    int tid = threadIdx.x;
    sr[tid] = row[tid];
    if (tid < H) { sy0[tid] = g_ui0[toff + tid]; sy1[tid] = g_ui1[toff + tid]; swy[tid] = g_uw[toff + tid]; }
    __syncthreads();
    float* ob = out + ((size_t)bn * 256 + t) * H * H;
    for (int p = tid * 4; p < H * H; p += 1024) {
        int y = p >> lg, xb = p & (H - 1);
        int y0 = sy0[y], y1 = sy1[y];
        float wy = swy[y], cwy = 1.f - wy;
        float r[4];
#pragma unroll
        for (int j = 0; j < 4; ++j) {
            int x = xb + j;
            int x0 = sy0[x], x1 = sy1[x];
            float wx = swy[x];
            float v00 = sr[y0 * 16 + x0], v01 = sr[y0 * 16 + x1];
            float v10 = sr[y1 * 16 + x0], v11 = sr[y1 * 16 + x1];
            float top = v00 * (1.f - wx) + v01 * wx;
            float bot = v10 * (1.f - wx) + v11 * wx;
            r[j] = top * cwy + bot * wy;
        }
        *(float4*)&ob[p] = make_float4(r[0], r[1], r[2], r[3]);
    }
}

// ============================ launch ===============================
extern "C" void kernel_launch(void* const* d_in, const int* in_sizes, int n_in,
                              void* d_out, int out_size) {
    const float* feat[5];
    for (int i = 0; i < 5; ++i) feat[i] = (const float*)d_in[i];
    const float* att   = (const float*)d_in[5];
    const float* ktw   = (const float*)d_in[6];
    const float* ktb   = (const float*)d_in[7];
    const float* vtw   = (const float*)d_in[8];
    const float* vtb   = (const float*)d_in[9];
    const float* kqw   = (const float*)d_in[10];
    const float* kqb   = (const float*)d_in[11];
    const float* vqw   = (const float*)d_in[12];
    const float* vqb   = (const float*)d_in[13];
    const float* bng   = (const float*)d_in[14];
    const float* bnb   = (const float*)d_in[15];
    const float* bnm   = (const float*)d_in[16];
    const float* bnv   = (const float*)d_in[17];
    const float* cw    = (const float*)d_in[18];
    const float* cb    = (const float*)d_in[19];
    float* out = (float*)d_out;

    static const int HWs[5]    = {4096, 1024, 256, 64, 16};
    static const int lg[5]     = {6, 5, 4, 3, 2};
    static const int toff[5]   = {0, 64, 96, 112, 120};
    static const int outoff[5] = {0, 2097152, 2621440, 2752512, 2785280};
    static const int attoff[5] = {2793472, 44736512, 55222272, 57843712, 58499072};

    FeatPtrs fp;
    for (int i = 0; i < 5; ++i) fp.p[i] = feat[i];

    k_tables<<<1, 256>>>();                         // 0
    k_wcat_att<<<1440, 256>>>(ktw, ktb, vtw, vtb);  // 1
    k_wcat_feat<<<7200, 256>>>(kqw, kqb, vqw, vqb); // 2
    k_w2s<<<1280, 256>>>(cw, bng, bnv);             // 3
    k_fs<<<2560, 256>>>(fp);                        // 4
    conv16<<<dim3(30, 10, 2), 256>>>(att);          // 5  <- ncu target
    k_cbias<<<5, 256>>>(cw, cb, bng, bnb, bnm, bnv);// 6
    reduce_all<<<4800, 256>>>();                    // 7
    k_logits<<<dim3(40, 4, 10), 256>>>();           // 8
    softmax_k<<<6400, 256>>>();                     // 9
    k_vt<<<dim3(4, 100), 256>>>();                  // 10
    vt_reduce<<<1280, 256>>>();                     // 11
    k_h<<<dim3(4, 4, 10), 256>>>();                 // 12

    for (int l = 0; l < 5; ++l) {
        int HW = HWs[l];
        int nT = (HW + 63) / 64;
        k_part1<<<dim3(2, nT, 2), 256>>>(cw, feat[l], out + outoff[l],
                                         HW, l, lg[l], toff[l]);
    }
    for (int l = 0; l < 5; ++l)
        attn_k<<<dim3(256, 40), 256>>>(out + attoff[l], l, lg[l], toff[l]);
}

// round 5
// speedup vs baseline: 1.3189x; 1.1078x over previous
#include <cuda_runtime.h>
#include <math.h>

typedef unsigned long long ull;

__device__ __forceinline__ ull pk2(float lo, float hi) {
    ull r; asm("mov.b64 %0, {%1, %2};" : "=l"(r) : "f"(lo), "f"(hi)); return r;
}
__device__ __forceinline__ void fma2(ull& d, ull a, ull b) {
    asm("fma.rn.f32x2 %0, %1, %2, %3;" : "=l"(d) : "l"(a), "l"(b), "l"(d));
}
__device__ __forceinline__ float2 up2(ull v) {
    float2 f; asm("mov.b64 {%0, %1}, %2;" : "=f"(f.x), "=f"(f.y) : "l"(v)); return f;
}

// ============================ constants ============================
__constant__ int d_H[5]    = {64, 32, 16, 8, 4};
__constant__ int d_TOFF[5] = {0, 64, 96, 112, 120};
__constant__ int c_ppre[6]   = {0, 64, 80, 84, 85, 86};     // part1 tile prefix
__constant__ int c_N[5]      = {4096, 1024, 256, 64, 16};
__constant__ int c_lg[5]     = {6, 5, 4, 3, 2};
__constant__ int c_outoff[5] = {0, 2097152, 2621440, 2752512, 2785280};

// ============================ scratch ==============================
__device__ float g_fs[655360];        // [fi(10)][cin 256][q 256]
__device__ float g_part[2457600];     // conv partials [cg 2][img 30][oc 160][pix 256]
__device__ float g_keytT[163840];     // [n][t][k]  (n 20, t 256, k 32)
__device__ float g_valtC[655360];     // [c 128][k 5120]
__device__ float g_kq[81920];         // [fi][k 32][q 256]
__device__ float g_final[655360];     // [fi][i 256][q 256]
__device__ float g_pT[13107200];      // [fi][n][t][q]
__device__ float g_vtpart[3276800];   // [z=kg*10+fi][c 128][t 256]
__device__ float g_h[655360];         // [fi][oc 256][q 256]
__device__ float g_W2sT[327680];      // [lvl][oc][i]
__device__ float g_cbias[1280];       // [lvl][oc]
__device__ float g_wAtt[368640];      // [oc 160][cin 256][9]
__device__ float g_bAtt[160];
__device__ float g_wF[1843200];       // [lvl][oc 160][cin 256][9]
__device__ float g_bF[800];
__device__ int   g_fi0[80], g_fi1[80];
__device__ float g_fw[80];            // H->16 tables
__device__ int   g_ui0[124], g_ui1[124];
__device__ float g_uw[124];           // 16->H tables

struct FeatPtrs { const float* p[5]; };

// ================== merged prep (1 launch) =========================
// bx ranges: [0,7200) wcat_feat | [7200,8640) wcat_att | [8640,9920) w2s
//            [9920,12480) fs    | [12480,12485) cbias  | 12485 tables
__global__ void __launch_bounds__(256) k_prep(
    FeatPtrs fp,
    const float* __restrict__ ktw, const float* __restrict__ ktb,
    const float* __restrict__ vtw, const float* __restrict__ vtb,
    const float* __restrict__ kqw, const float* __restrict__ kqb,
    const float* __restrict__ vqw, const float* __restrict__ vqb,
    const float* __restrict__ bng, const float* __restrict__ bnb,
    const float* __restrict__ bnm, const float* __restrict__ bnv,
    const float* __restrict__ cw,  const float* __restrict__ cb) {
    int bx = blockIdx.x, tid = threadIdx.x;
    if (bx < 7200) {                                   // wcat_feat
        int idx = bx * 256 + tid;
        if (idx < 1843200) {
            int lvl = idx / 368640, r2 = idx % 368640;
            int oc = r2 / 2304, r = r2 % 2304;
            g_wF[idx] = (oc < 32) ? kqw[(lvl * 32 + oc) * 2304 + r]
                                  : vqw[(lvl * 128 + oc - 32) * 2304 + r];
        }
        if (idx < 800) {
            int lvl = idx / 160, oc = idx % 160;
            g_bF[idx] = (oc < 32) ? kqb[lvl * 32 + oc] : vqb[lvl * 128 + oc - 32];
        }
    } else if (bx < 8640) {                            // wcat_att
        int idx = (bx - 7200) * 256 + tid;
        if (idx < 368640) {
            int oc = idx / 2304, r = idx % 2304;
            g_wAtt[idx] = (oc < 32) ? ktw[oc * 2304 + r] : vtw[(oc - 32) * 2304 + r];
        }
        if (idx < 160) g_bAtt[idx] = (idx < 32) ? ktb[idx] : vtb[idx - 32];
    } else if (bx < 9920) {                            // w2s
        int idx = (bx - 8640) * 256 + tid;
        int lvl = idx >> 16, r = idx & 65535, oc = r >> 8, i = r & 255;
        float sc = bng[lvl * 256 + i] / sqrtf(bnv[lvl * 256 + i] + 1e-5f);
        g_W2sT[idx] = cw[oc * 512 + 256 + i] * sc;
    } else if (bx < 12480) {                           // fs (needs tables: inline compute)
        int idx = (bx - 9920) * 256 + tid;             // < 655360
        int q = idx & 255, c = (idx >> 8) & 255, img = idx >> 16;
        int lvl = img >> 1, b = img & 1;
        int H = d_H[lvl];
        float r = (float)((double)(H - 1) / 15.0);
        int yq = q >> 4, xq = q & 15;
        float sy = yq * r, sx = xq * r;
        int y0 = min((int)floorf(sy), H - 1), x0 = min((int)floorf(sx), H - 1);
        int y1 = min(y0 + 1, H - 1), x1 = min(x0 + 1, H - 1);
        float wy = sy - y0, wx = sx - x0;
        const float* src = fp.p[lvl] + ((size_t)(b * 256 + c)) * H * H;
        float v00 = src[y0 * H + x0], v01 = src[y0 * H + x1];
        float v10 = src[y1 * H + x0], v11 = src[y1 * H + x1];
        float top = v00 * (1.f - wx) + v01 * wx;
        float bot = v10 * (1.f - wx) + v11 * wx;
        g_fs[idx] = top * (1.f - wy) + bot * wy;
    } else if (bx < 12485) {                           // cbias
        int lvl = bx - 12480, oc = tid;
        float s = 0.f;
        for (int i = 0; i < 256; ++i) {
            float sc = bng[lvl * 256 + i] / sqrtf(bnv[lvl * 256 + i] + 1e-5f);
            s += cw[oc * 512 + 256 + i] * (bnb[lvl * 256 + i] - sc * bnm[lvl * 256 + i]);
        }
        g_cbias[lvl * 256 + oc] = cb[oc] + s;
    } else {                                           // tables
        if (tid < 80) {
            int lvl = tid >> 4, o = tid & 15;
            int H = d_H[lvl];
            float r = (float)((double)(H - 1) / 15.0);
            float s = (float)o * r;
            int i0 = min((int)floorf(s), H - 1);
            int i1 = min(i0 + 1, H - 1);
            g_fi0[tid] = i0; g_fi1[tid] = i1; g_fw[tid] = s - (float)i0;
        }
        if (tid >= 128 && tid < 252) {
            int j = tid - 128;
            int lvl = (j < 64) ? 0 : (j < 96) ? 1 : (j < 112) ? 2 : (j < 120) ? 3 : 4;
            int o = j - d_TOFF[lvl];
            int H = d_H[lvl];
            float r = (float)(15.0 / (double)(H - 1));
            float s = (float)o * r;
            int i0 = min((int)floorf(s), 15);
            int i1 = min(i0 + 1, 15);
            g_ui0[j] = i0; g_ui1[j] = i1; g_uw[j] = s - (float)i0;
        }
    }
}

// ===== 3x3 SAME conv on 16x16 (FFMA2), att(20)+feat(10) imgs =======
// grid (30, 10, 2): x=img, y=16-oc group, z=128-cin group
__global__ void __launch_bounds__(256) conv16(const float* __restrict__ att) {
    int img = blockIdx.x, grp = blockIdx.y, cg = blockIdx.z;
    const float* inp; const float* wb;
    if (img < 20) {
        inp = att + (size_t)img * 65536 + (size_t)cg * 32768;
        wb  = g_wAtt + (size_t)grp * 16 * 2304 + (size_t)cg * 1152;
    } else {
        int fi = img - 20;
        inp = g_fs + (size_t)fi * 65536 + (size_t)cg * 32768;
        wb  = g_wF + (size_t)(fi >> 1) * 368640 + (size_t)grp * 16 * 2304 + (size_t)cg * 1152;
    }
    float* outp = g_part + (((size_t)cg * 30 + img) * 160 + grp * 16) * 256;

    __shared__ float tile[8][18][18];
    __shared__ __align__(16) float wsh[8][9][16];
    int tid = threadIdx.x;
    for (int i = tid; i < 8 * 18 * 18; i += 256) ((float*)tile)[i] = 0.f;

    ull acc[8] = {};
    int y = tid >> 4, x = tid & 15;

    for (int cc = 0; cc < 128; cc += 8) {
        __syncthreads();
#pragma unroll
        for (int i = 0; i < 8; ++i) {
            int idx = tid + i * 256;
            int c = idx >> 8, p = idx & 255;
            tile[c][(p >> 4) + 1][(p & 15) + 1] = inp[(cc + c) * 256 + p];
        }
#pragma unroll
        for (int i = 0; i < 5; ++i) {
            int idx = tid + i * 256;
            if (idx < 1152) {
                int c = idx / 144, r = idx % 144;
                int tap = r / 16, oc = r % 16;
                wsh[c][tap][oc] = wb[(size_t)oc * 2304 + (cc + c) * 9 + tap];
            }
        }
        __syncthreads();
#pragma unroll
        for (int c = 0; c < 8; ++c) {
            float v[9];
#pragma unroll
            for (int dy = 0; dy < 3; ++dy)
#pragma unroll
                for (int dx = 0; dx < 3; ++dx)
                    v[dy * 3 + dx] = tile[c][y + dy][x + dx];
#pragma unroll
            for (int tap = 0; tap < 9; ++tap) {
                ull vv = pk2(v[tap], v[tap]);
                const ulonglong2* wp = (const ulonglong2*)&wsh[c][tap][0];
#pragma unroll
                for (int j = 0; j < 4; ++j) {
                    ulonglong2 w2 = wp[j];
                    fma2(acc[2 * j], vv, w2.x);
                    fma2(acc[2 * j + 1], vv, w2.y);
                }
            }
        }
    }
#pragma unroll
    for (int j = 0; j < 8; ++j) {
        float2 f = up2(acc[j]);
        outp[(2 * j) * 256 + tid]     = f.x;
        outp[(2 * j + 1) * 256 + tid] = f.y;
    }
}

// ================ merged partial reduction + layout ================
__global__ void __launch_bounds__(256) reduce_all() {
    int idx = blockIdx.x * 256 + threadIdx.x;          // < 1228800
    int img = idx / 40960, r = idx % 40960;
    int oc = r >> 8, pix = r & 255;
    float s = g_part[idx] + g_part[1228800 + idx];
    if (img < 20) {
        s += g_bAtt[oc];
        if (oc < 32) g_keytT[((size_t)img * 256 + pix) * 32 + oc] = s;
        else         g_valtC[((size_t)(oc - 32) * 20 + img) * 256 + pix] = s;
    } else {
        int fi = img - 20, lvl = fi >> 1;
        s += g_bF[lvl * 160 + oc];
        if (oc < 32) g_kq[((size_t)fi * 32 + oc) * 256 + pix] = s;
        else         g_final[((size_t)fi * 256 + (oc - 32)) * 256 + pix] = 20.f * s;
    }
}

// ============ logits (FFMA2): pT[nt][q] = keytT[nt][k]*kq[k][q] ====
// grid (40, 4, 10): m0=bx*128, q0=by*64, z=fi. K=32 single tile.
__global__ void __launch_bounds__(256) k_logits() {
    int m0 = blockIdx.x * 128, q0 = blockIdx.y * 64;
    int fi = blockIdx.z;
    const float* B = g_kq + (size_t)fi * 8192;
    float* C = g_pT + (size_t)fi * 1310720;
    __shared__ ull As2[32][132];
    __shared__ __align__(16) float Bs[32][64];
    int tid = threadIdx.x, tx = tid & 15, ty = tid >> 4;

#pragma unroll
    for (int i = 0; i < 4; ++i) {                       // A: 128x32 dup-pairs
        int u = tid + i * 256;
        int rr = u >> 3, ko = (u & 7) * 4;
        float4 av = *(const float4*)&g_keytT[(size_t)(m0 + rr) * 32 + ko];
        As2[ko + 0][rr] = pk2(av.x, av.x);
        As2[ko + 1][rr] = pk2(av.y, av.y);
        As2[ko + 2][rr] = pk2(av.z, av.z);
        As2[ko + 3][rr] = pk2(av.w, av.w);
    }
#pragma unroll
    for (int i = 0; i < 8; ++i) {                       // B: 32x64
        int e = tid + i * 256;
        int n = e & 63, kk = e >> 6;
        Bs[kk][n] = B[(size_t)kk * 256 + q0 + n];
    }
    __syncthreads();

    ull acc[8][2] = {};
#pragma unroll
    for (int kk = 0; kk < 32; ++kk) {
        ulonglong2 bb = *(const ulonglong2*)&Bs[kk][tx * 4];
#pragma unroll
        for (int i = 0; i < 8; ++i) {
            ull a = As2[kk][ty * 8 + i];
            fma2(acc[i][0], a, bb.x);
            fma2(acc[i][1], a, bb.y);
        }
    }
#pragma unroll
    for (int i = 0; i < 8; ++i) {
        ulonglong2 s; s.x = acc[i][0]; s.y = acc[i][1];
        *(ulonglong2*)&C[(size_t)(m0 + ty * 8 + i) * 256 + q0 + tx * 4] = s;
    }
}

// ===================== softmax over q ==============================
__global__ void __launch_bounds__(256) softmax_k() {
    int w = threadIdx.x >> 5, lane = threadIdx.x & 31;
    size_t r = (size_t)blockIdx.x * 8 + w;              // < 51200
    float* row = g_pT + r * 256;
    float v[8];
    float mx = -1e30f;
#pragma unroll
    for (int i = 0; i < 8; ++i) { v[i] = row[lane + i * 32]; mx = fmaxf(mx, v[i]); }
#pragma unroll
    for (int o = 16; o > 0; o >>= 1) mx = fmaxf(mx, __shfl_xor_sync(0xffffffffu, mx, o));
    float s = 0.f;
#pragma unroll
    for (int i = 0; i < 8; ++i) { v[i] = __expf(v[i] - mx); s += v[i]; }
#pragma unroll
    for (int o = 16; o > 0; o >>= 1) s += __shfl_xor_sync(0xffffffffu, s, o);
    float inv = 1.f / s;
#pragma unroll
    for (int i = 0; i < 8; ++i) row[lane + i * 32] = v[i] * inv;
}

// ====== vt (FFMA2): C[c][t] += valtC[c][k]*pT[t,k], splitK=10 ======
// grid (4, 100): t0=bx*64, by = kg*10+fi
__global__ void __launch_bounds__(256) k_vt() {
    int t0 = blockIdx.x * 64;
    int z = blockIdx.y, fi = z % 10, kg = z / 10;
    const float* Bp = g_pT + (size_t)fi * 1310720;
    float* Cp = g_vtpart + (size_t)z * 32768;
    __shared__ ull As2[16][132];
    __shared__ __align__(16) float Bs[16][64];
    int tid = threadIdx.x, tx = tid & 15, ty = tid >> 4;
    ull acc[8][2] = {};

    int kbase = kg * 512;
    for (int k0 = kbase; k0 < kbase + 512; k0 += 16) {
        __syncthreads();
        {
            int rr = tid >> 1;
#pragma unroll
            for (int e0 = 0; e0 < 2; ++e0) {
                int ko = (tid & 1) * 4 + e0 * 8;
                float4 av = *(const float4*)&g_valtC[(size_t)rr * 5120 + k0 + ko];
                As2[ko + 0][rr] = pk2(av.x, av.x);
                As2[ko + 1][rr] = pk2(av.y, av.y);
                As2[ko + 2][rr] = pk2(av.z, av.z);
                As2[ko + 3][rr] = pk2(av.w, av.w);
            }
        }
        {
            int nblk = k0 >> 8, a0 = k0 & 255;
            const float* Bn = Bp + (size_t)nblk * 65536 + a0;
            int tt = tid >> 2, kk0 = (tid & 3) * 4;
            float4 bv = *(const float4*)&Bn[(size_t)(t0 + tt) * 256 + kk0];
            Bs[kk0 + 0][tt] = bv.x; Bs[kk0 + 1][tt] = bv.y;
            Bs[kk0 + 2][tt] = bv.z; Bs[kk0 + 3][tt] = bv.w;
        }
        __syncthreads();
#pragma unroll
        for (int kk = 0; kk < 16; ++kk) {
            ulonglong2 bb = *(const ulonglong2*)&Bs[kk][tx * 4];
#pragma unroll
            for (int i = 0; i < 8; ++i) {
                ull a = As2[kk][ty * 8 + i];
                fma2(acc[i][0], a, bb.x);
                fma2(acc[i][1], a, bb.y);
            }
        }
    }
#pragma unroll
    for (int i = 0; i < 8; ++i) {
        ulonglong2 s; s.x = acc[i][0]; s.y = acc[i][1];
        *(ulonglong2*)&Cp[(size_t)(ty * 8 + i) * 256 + t0 + tx * 4] = s;
    }
}

__global__ void __launch_bounds__(256) vt_reduce() {
    int idx = blockIdx.x * 256 + threadIdx.x;          // < 327680
    int fi = idx >> 15, r = idx & 32767;
    float s = 0.f;
#pragma unroll
    for (int kg = 0; kg < 10; ++kg) s += g_vtpart[((size_t)(kg * 10 + fi) << 15) + r];
    int c = r >> 8, t = r & 255;
    g_final[((size_t)fi * 256 + 128 + c) * 256 + t] = s;
}

// ============ h = W2sT * final (FFMA2, 128x64 tiles) ===============
// grid (2, 4, 10)
__global__ void __launch_bounds__(256) k_h() {
    int z = blockIdx.z;
    const float* A = g_W2sT + (size_t)(z >> 1) * 65536;
    const float* B = g_final + (size_t)z * 65536;
    float* C = g_h + (size_t)z * 65536;
    int m0 = blockIdx.x * 128, n0 = blockIdx.y * 64;
    __shared__ ull As2[16][132];
    __shared__ __align__(16) float Bs[16][64];
    int tid = threadIdx.x, tx = tid & 15, ty = tid >> 4;
    ull acc[8][2] = {};

    for (int k0 = 0; k0 < 256; k0 += 16) {
        __syncthreads();
        {
            int rr = tid >> 1;
#pragma unroll
            for (int e0 = 0; e0 < 2; ++e0) {
                int ko = (tid & 1) * 4 + e0 * 8;
                float4 av = *(const float4*)&A[(size_t)(m0 + rr) * 256 + k0 + ko];
                As2[ko + 0][rr] = pk2(av.x, av.x);
                As2[ko + 1][rr] = pk2(av.y, av.y);
                As2[ko + 2][rr] = pk2(av.z, av.z);
                As2[ko + 3][rr] = pk2(av.w, av.w);
            }
        }
        {
            int nn = tid & 63, kk = tid >> 6;           // 4 kk per pass
#pragma unroll
            for (int e0 = 0; e0 < 4; ++e0)
                Bs[kk + e0 * 4][nn] = B[(size_t)(k0 + kk + e0 * 4) * 256 + n0 + nn];
        }
        __syncthreads();
#pragma unroll
        for (int kk = 0; kk < 16; ++kk) {
            ulonglong2 bb = *(const ulonglong2*)&Bs[kk][tx * 4];
#pragma unroll
            for (int i = 0; i < 8; ++i) {
                ull a = As2[kk][ty * 8 + i];
                fma2(acc[i][0], a, bb.x);
                fma2(acc[i][1], a, bb.y);
            }
        }
    }
#pragma unroll
    for (int i = 0; i < 8; ++i) {
        ulonglong2 s; s.x = acc[i][0]; s.y = acc[i][1];
        *(ulonglong2*)&C[(size_t)(m0 + ty * 8 + i) * 256 + n0 + tx * 4] = s;
    }
}

// == part1 (FFMA2, fused levels): out = W1*feat + up16(h) + cbias ===
// grid (2, 86, 2): y decodes (lvl, n-tile)
__global__ void __launch_bounds__(256) k_part1(const float* __restrict__ cw,
                                               FeatPtrs fp, float* __restrict__ out) {
    int yb = blockIdx.y;
    int lvl = 0;
    while (yb >= c_ppre[lvl + 1]) ++lvl;
    int n0 = (yb - c_ppre[lvl]) * 64;
    int N = c_N[lvl], lgW = c_lg[lvl], toff = d_TOFF[lvl];
    int m0 = blockIdx.x * 128, b = blockIdx.z;
    const float* Bb = fp.p[lvl] + (size_t)b * 256 * N;
    float* Cb = out + (size_t)c_outoff[lvl] + (size_t)b * 256 * N;
    int img = lvl * 2 + b;
    __shared__ ull As2[16][132];
    __shared__ __align__(16) float Bs[16][64];
    int tid = threadIdx.x, tx = tid & 15, ty = tid >> 4;
    ull acc[8][2] = {};

    for (int k0 = 0; k0 < 256; k0 += 16) {
        __syncthreads();
        {
            int rr = tid >> 1;
#pragma unroll
            for (int e0 = 0; e0 < 2; ++e0) {
                int ko = (tid & 1) * 4 + e0 * 8;
                float4 av = *(const float4*)&cw[(size_t)(m0 + rr) * 512 + k0 + ko];
                As2[ko + 0][rr] = pk2(av.x, av.x);
                As2[ko + 1][rr] = pk2(av.y, av.y);
                As2[ko + 2][rr] = pk2(av.z, av.z);
                As2[ko + 3][rr] = pk2(av.w, av.w);
            }
        }
        {
            int nn = tid & 63, kk = tid >> 6;
#pragma unroll
            for (int e0 = 0; e0 < 4; ++e0) {
                int p = n0 + nn;
                float bv = 0.f;
                if (p < N) bv = Bb[(size_t)(k0 + kk + e0 * 4) * N + p];
                Bs[kk + e0 * 4][nn] = bv;
            }
        }
        __syncthreads();
#pragma unroll
        for (int kk = 0; kk < 16; ++kk) {
            ulonglong2 bb = *(const ulonglong2*)&Bs[kk][tx * 4];
#pragma unroll
            for (int i = 0; i < 8; ++i) {
                ull a = As2[kk][ty * 8 + i];
                fma2(acc[i][0], a, bb.x);
                fma2(acc[i][1], a, bb.y);
            }
        }
    }

    int Wm = (1 << lgW) - 1;
#pragma unroll
    for (int i = 0; i < 8; ++i) {
        int oc = m0 + ty * 8 + i;
        float cbv = g_cbias[lvl * 256 + oc];
        const float* hrow = g_h + ((size_t)img * 256 + oc) * 256;
        float2 f0 = up2(acc[i][0]), f1 = up2(acc[i][1]);
        float av[4] = {f0.x, f0.y, f1.x, f1.y};
#pragma unroll
        for (int j = 0; j < 4; ++j) {
            int p = n0 + tx * 4 + j;
            if (p < N) {
                int yy = p >> lgW, xx = p & Wm;
                int y0 = g_ui0[toff + yy], y1 = g_ui1[toff + yy];
                int x0 = g_ui0[toff + xx], x1 = g_ui1[toff + xx];
                float wy = g_uw[toff + yy], wx = g_uw[toff + xx];
                float v00 = hrow[y0 * 16 + x0], v01 = hrow[y0 * 16 + x1];
                float v10 = hrow[y1 * 16 + x0], v11 = hrow[y1 * 16 + x1];
                float top = v00 * (1.f - wx) + v01 * wx;
                float bot = v10 * (1.f - wx) + v11 * wx;
                Cb[(size_t)oc * N + p] = av[j] + top * (1.f - wy) + bot * wy + cbv;
            }
        }
    }
}

// ===================== attention upsample (float4) =================
__global__ void __launch_bounds__(256) attn_k(float* __restrict__ out,
                                              int lvl, int lg, int toff) {
    int H = 1 << lg;
    int t = blockIdx.x, bn = blockIdx.y;
    int b = bn / 20, n = bn - b * 20;
    int img = lvl * 2 + b;
    const float* row = g_pT + ((size_t)((img * 20 + n) * 256 + t)) * 256;
    __shared__ float sr[256];
    __shared__ int sy0[64], sy1[64];
    __shared__ float swy[64];
    int tid = threadIdx.x;
    sr[tid] = row[tid];
    if (tid < H) { sy0[tid] = g_ui0[toff + tid]; sy1[tid] = g_ui1[toff + tid]; swy[tid] = g_uw[toff + tid]; }
    __syncthreads();
    float* ob = out + ((size_t)bn * 256 + t) * H * H;
    for (int p = tid * 4; p < H * H; p += 1024) {
        int y = p >> lg, xb = p & (H - 1);
        int y0 = sy0[y], y1 = sy1[y];
        float wy = swy[y], cwy = 1.f - wy;
        float r[4];
#pragma unroll
        for (int j = 0; j < 4; ++j) {
            int x = xb + j;
            int x0 = sy0[x], x1 = sy1[x];
            float wx = swy[x];
            float v00 = sr[y0 * 16 + x0], v01 = sr[y0 * 16 + x1];
            float v10 = sr[y1 * 16 + x0], v11 = sr[y1 * 16 + x1];
            float top = v00 * (1.f - wx) + v01 * wx;
            float bot = v10 * (1.f - wx) + v11 * wx;
            r[j] = top * cwy + bot * wy;
        }
        *(float4*)&ob[p] = make_float4(r[0], r[1], r[2], r[3]);
    }
}

// ============================ launch ===============================
extern "C" void kernel_launch(void* const* d_in, const int* in_sizes, int n_in,
                              void* d_out, int out_size) {
    const float* feat[5];
    for (int i = 0; i < 5; ++i) feat[i] = (const float*)d_in[i];
    const float* att = (const float*)d_in[5];
    const float* cw  = (const float*)d_in[18];
    float* out = (float*)d_out;

    static const int lgs[5]    = {6, 5, 4, 3, 2};
    static const int toffs[5]  = {0, 64, 96, 112, 120};
    static const int attoff[5] = {2793472, 44736512, 55222272, 57843712, 58499072};

    FeatPtrs fp;
    for (int i = 0; i < 5; ++i) fp.p[i] = feat[i];

    k_prep<<<12486, 256>>>(fp,
        (const float*)d_in[6],  (const float*)d_in[7],
        (const float*)d_in[8],  (const float*)d_in[9],
        (const float*)d_in[10], (const float*)d_in[11],
        (const float*)d_in[12], (const float*)d_in[13],
        (const float*)d_in[14], (const float*)d_in[15],
        (const float*)d_in[16], (const float*)d_in[17],
        cw, (const float*)d_in[19]);
    conv16<<<dim3(30, 10, 2), 256>>>(att);
    reduce_all<<<4800, 256>>>();
    k_logits<<<dim3(40, 4, 10), 256>>>();
    softmax_k<<<6400, 256>>>();
    k_vt<<<dim3(4, 100), 256>>>();
    vt_reduce<<<1280, 256>>>();
    k_h<<<dim3(2, 4, 10), 256>>>();
    k_part1<<<dim3(2, 86, 2), 256>>>(cw, fp, out);
    for (int l = 0; l < 5; ++l)
        attn_k<<<dim3(256, 40), 256>>>(out + attoff[l], l, lgs[l], toffs[l]);
}

// round 6
// speedup vs baseline: 1.3210x; 1.0015x over previous
#include <cuda_runtime.h>
#include <math.h>

typedef unsigned long long ull;

__device__ __forceinline__ ull pk2(float lo, float hi) {
    ull r; asm("mov.b64 %0, {%1, %2};" : "=l"(r) : "f"(lo), "f"(hi)); return r;
}
__device__ __forceinline__ void fma2(ull& d, ull a, ull b) {
    asm("fma.rn.f32x2 %0, %1, %2, %3;" : "=l"(d) : "l"(a), "l"(b), "l"(d));
}
__device__ __forceinline__ float2 up2(ull v) {
    float2 f; asm("mov.b64 {%0, %1}, %2;" : "=f"(f.x), "=f"(f.y) : "l"(v)); return f;
}

// ============================ constants ============================
__constant__ int d_H[5]    = {64, 32, 16, 8, 4};
__constant__ int d_TOFF[5] = {0, 64, 96, 112, 120};
__constant__ int c_ppre[6]   = {0, 64, 80, 84, 85, 86};     // part1 tile prefix
__constant__ int c_N[5]      = {4096, 1024, 256, 64, 16};
__constant__ int c_lg[5]     = {6, 5, 4, 3, 2};
__constant__ int c_outoff[5] = {0, 2097152, 2621440, 2752512, 2785280};

// ============================ scratch ==============================
__device__ float g_fs[655360];        // [fi(10)][cin 256][q 256]
__device__ float g_part[2457600];     // conv partials [cg 2][img 30][oc 160][pix 256]
__device__ float g_keytT[163840];     // [n][t][k]  (n 20, t 256, k 32)
__device__ float g_valtC[655360];     // [c 128][k 5120]
__device__ float g_kq[81920];         // [fi][k 32][q 256]
__device__ float g_final[655360];     // [fi][i 256][q 256]
__device__ float g_pT[13107200];      // [fi][n][t][q]
__device__ float g_vtpart[3276800];   // [z=kg*10+fi][c 128][t 256]
__device__ float g_h[655360];         // [fi][oc 256][q 256]
__device__ float g_W2sT[327680];      // [lvl][oc][i]
__device__ float g_cbias[1280];       // [lvl][oc]
__device__ float g_wAtt[368640];      // [oc 160][cin 256][9]
__device__ float g_bAtt[160];
__device__ float g_wF[1843200];       // [lvl][oc 160][cin 256][9]
__device__ float g_bF[800];
__device__ int   g_fi0[80], g_fi1[80];
__device__ float g_fw[80];            // H->16 tables
__device__ int   g_ui0[124], g_ui1[124];
__device__ float g_uw[124];           // 16->H tables

struct FeatPtrs { const float* p[5]; };

// ================== merged prep (1 launch) =========================
// bx ranges: [0,7200) wcat_feat | [7200,8640) wcat_att | [8640,9920) w2s
//            [9920,12480) fs    | [12480,12485) cbias  | 12485 tables
__global__ void __launch_bounds__(256) k_prep(
    FeatPtrs fp,
    const float* __restrict__ ktw, const float* __restrict__ ktb,
    const float* __restrict__ vtw, const float* __restrict__ vtb,
    const float* __restrict__ kqw, const float* __restrict__ kqb,
    const float* __restrict__ vqw, const float* __restrict__ vqb,
    const float* __restrict__ bng, const float* __restrict__ bnb,
    const float* __restrict__ bnm, const float* __restrict__ bnv,
    const float* __restrict__ cw,  const float* __restrict__ cb) {
    int bx = blockIdx.x, tid = threadIdx.x;
    if (bx < 7200) {                                   // wcat_feat
        int idx = bx * 256 + tid;
        if (idx < 1843200) {
            int lvl = idx / 368640, r2 = idx % 368640;
            int oc = r2 / 2304, r = r2 % 2304;
            g_wF[idx] = (oc < 32) ? kqw[(lvl * 32 + oc) * 2304 + r]
                                  : vqw[(lvl * 128 + oc - 32) * 2304 + r];
        }
        if (idx < 800) {
            int lvl = idx / 160, oc = idx % 160;
            g_bF[idx] = (oc < 32) ? kqb[lvl * 32 + oc] : vqb[lvl * 128 + oc - 32];
        }
    } else if (bx < 8640) {                            // wcat_att
        int idx = (bx - 7200) * 256 + tid;
        if (idx < 368640) {
            int oc = idx / 2304, r = idx % 2304;
            g_wAtt[idx] = (oc < 32) ? ktw[oc * 2304 + r] : vtw[(oc - 32) * 2304 + r];
        }
        if (idx < 160) g_bAtt[idx] = (idx < 32) ? ktb[idx] : vtb[idx - 32];
    } else if (bx < 9920) {                            // w2s
        int idx = (bx - 8640) * 256 + tid;
        int lvl = idx >> 16, r = idx & 65535, oc = r >> 8, i = r & 255;
        float sc = bng[lvl * 256 + i] / sqrtf(bnv[lvl * 256 + i] + 1e-5f);
        g_W2sT[idx] = cw[oc * 512 + 256 + i] * sc;
    } else if (bx < 12480) {                           // fs (needs tables: inline compute)
        int idx = (bx - 9920) * 256 + tid;             // < 655360
        int q = idx & 255, c = (idx >> 8) & 255, img = idx >> 16;
        int lvl = img >> 1, b = img & 1;
        int H = d_H[lvl];
        float r = (float)((double)(H - 1) / 15.0);
        int yq = q >> 4, xq = q & 15;
        float sy = yq * r, sx = xq * r;
        int y0 = min((int)floorf(sy), H - 1), x0 = min((int)floorf(sx), H - 1);
        int y1 = min(y0 + 1, H - 1), x1 = min(x0 + 1, H - 1);
        float wy = sy - y0, wx = sx - x0;
        const float* src = fp.p[lvl] + ((size_t)(b * 256 + c)) * H * H;
        float v00 = src[y0 * H + x0], v01 = src[y0 * H + x1];
        float v10 = src[y1 * H + x0], v11 = src[y1 * H + x1];
        float top = v00 * (1.f - wx) + v01 * wx;
        float bot = v10 * (1.f - wx) + v11 * wx;
        g_fs[idx] = top * (1.f - wy) + bot * wy;
    } else if (bx < 12485) {                           // cbias
        int lvl = bx - 12480, oc = tid;
        float s = 0.f;
        for (int i = 0; i < 256; ++i) {
            float sc = bng[lvl * 256 + i] / sqrtf(bnv[lvl * 256 + i] + 1e-5f);
            s += cw[oc * 512 + 256 + i] * (bnb[lvl * 256 + i] - sc * bnm[lvl * 256 + i]);
        }
        g_cbias[lvl * 256 + oc] = cb[oc] + s;
    } else {                                           // tables
        if (tid < 80) {
            int lvl = tid >> 4, o = tid & 15;
            int H = d_H[lvl];
            float r = (float)((double)(H - 1) / 15.0);
            float s = (float)o * r;
            int i0 = min((int)floorf(s), H - 1);
            int i1 = min(i0 + 1, H - 1);
            g_fi0[tid] = i0; g_fi1[tid] = i1; g_fw[tid] = s - (float)i0;
        }
        if (tid >= 128 && tid < 252) {
            int j = tid - 128;
            int lvl = (j < 64) ? 0 : (j < 96) ? 1 : (j < 112) ? 2 : (j < 120) ? 3 : 4;
            int o = j - d_TOFF[lvl];
            int H = d_H[lvl];
            float r = (float)(15.0 / (double)(H - 1));
            float s = (float)o * r;
            int i0 = min((int)floorf(s), 15);
            int i1 = min(i0 + 1, 15);
            g_ui0[j] = i0; g_ui1[j] = i1; g_uw[j] = s - (float)i0;
        }
    }
}

// ===== 3x3 SAME conv on 16x16 (FFMA2), att(20)+feat(10) imgs =======
// grid (30, 10, 2): x=img, y=16-oc group, z=128-cin group
__global__ void __launch_bounds__(256) conv16(const float* __restrict__ att) {
    int img = blockIdx.x, grp = blockIdx.y, cg = blockIdx.z;
    const float* inp; const float* wb;
    if (img < 20) {
        inp = att + (size_t)img * 65536 + (size_t)cg * 32768;
        wb  = g_wAtt + (size_t)grp * 16 * 2304 + (size_t)cg * 1152;
    } else {
        int fi = img - 20;
        inp = g_fs + (size_t)fi * 65536 + (size_t)cg * 32768;
        wb  = g_wF + (size_t)(fi >> 1) * 368640 + (size_t)grp * 16 * 2304 + (size_t)cg * 1152;
    }
    float* outp = g_part + (((size_t)cg * 30 + img) * 160 + grp * 16) * 256;

    __shared__ float tile[8][18][18];
    __shared__ __align__(16) float wsh[8][9][16];
    int tid = threadIdx.x;
    for (int i = tid; i < 8 * 18 * 18; i += 256) ((float*)tile)[i] = 0.f;

    ull acc[8] = {};
    int y = tid >> 4, x = tid & 15;

    for (int cc = 0; cc < 128; cc += 8) {
        __syncthreads();
#pragma unroll
        for (int i = 0; i < 8; ++i) {
            int idx = tid + i * 256;
            int c = idx >> 8, p = idx & 255;
            tile[c][(p >> 4) + 1][(p & 15) + 1] = inp[(cc + c) * 256 + p];
        }
#pragma unroll
        for (int i = 0; i < 5; ++i) {
            int idx = tid + i * 256;
            if (idx < 1152) {
                int c = idx / 144, r = idx % 144;
                int tap = r / 16, oc = r % 16;
                wsh[c][tap][oc] = wb[(size_t)oc * 2304 + (cc + c) * 9 + tap];
            }
        }
        __syncthreads();
#pragma unroll
        for (int c = 0; c < 8; ++c) {
            float v[9];
#pragma unroll
            for (int dy = 0; dy < 3; ++dy)
#pragma unroll
                for (int dx = 0; dx < 3; ++dx)
                    v[dy * 3 + dx] = tile[c][y + dy][x + dx];
#pragma unroll
            for (int tap = 0; tap < 9; ++tap) {
                ull vv = pk2(v[tap], v[tap]);
                const ulonglong2* wp = (const ulonglong2*)&wsh[c][tap][0];
#pragma unroll
                for (int j = 0; j < 4; ++j) {
                    ulonglong2 w2 = wp[j];
                    fma2(acc[2 * j], vv, w2.x);
                    fma2(acc[2 * j + 1], vv, w2.y);
                }
            }
        }
    }
#pragma unroll
    for (int j = 0; j < 8; ++j) {
        float2 f = up2(acc[j]);
        outp[(2 * j) * 256 + tid]     = f.x;
        outp[(2 * j + 1) * 256 + tid] = f.y;
    }
}

// ================ merged partial reduction + layout ================
__global__ void __launch_bounds__(256) reduce_all() {
    int idx = blockIdx.x * 256 + threadIdx.x;          // < 1228800
    int img = idx / 40960, r = idx % 40960;
    int oc = r >> 8, pix = r & 255;
    float s = g_part[idx] + g_part[1228800 + idx];
    if (img < 20) {
        s += g_bAtt[oc];
        if (oc < 32) g_keytT[((size_t)img * 256 + pix) * 32 + oc] = s;
        else         g_valtC[((size_t)(oc - 32) * 20 + img) * 256 + pix] = s;
    } else {
        int fi = img - 20, lvl = fi >> 1;
        s += g_bF[lvl * 160 + oc];
        if (oc < 32) g_kq[((size_t)fi * 32 + oc) * 256 + pix] = s;
        else         g_final[((size_t)fi * 256 + (oc - 32)) * 256 + pix] = 20.f * s;
    }
}

// ============ logits (FFMA2): pT[nt][q] = keytT[nt][k]*kq[k][q] ====
// grid (40, 4, 10): m0=bx*128, q0=by*64, z=fi. K=32 single tile.
__global__ void __launch_bounds__(256) k_logits() {
    int m0 = blockIdx.x * 128, q0 = blockIdx.y * 64;
    int fi = blockIdx.z;
    const float* B = g_kq + (size_t)fi * 8192;
    float* C = g_pT + (size_t)fi * 1310720;
    __shared__ ull As2[32][132];
    __shared__ __align__(16) float Bs[32][64];
    int tid = threadIdx.x, tx = tid & 15, ty = tid >> 4;

#pragma unroll
    for (int i = 0; i < 4; ++i) {                       // A: 128x32 dup-pairs
        int u = tid + i * 256;
        int rr = u >> 3, ko = (u & 7) * 4;
        float4 av = *(const float4*)&g_keytT[(size_t)(m0 + rr) * 32 + ko];
        As2[ko + 0][rr] = pk2(av.x, av.x);
        As2[ko + 1][rr] = pk2(av.y, av.y);
        As2[ko + 2][rr] = pk2(av.z, av.z);
        As2[ko + 3][rr] = pk2(av.w, av.w);
    }
#pragma unroll
    for (int i = 0; i < 8; ++i) {                       // B: 32x64
        int e = tid + i * 256;
        int n = e & 63, kk = e >> 6;
        Bs[kk][n] = B[(size_t)kk * 256 + q0 + n];
    }
    __syncthreads();

    ull acc[8][2] = {};
#pragma unroll
    for (int kk = 0; kk < 32; ++kk) {
        ulonglong2 bb = *(const ulonglong2*)&Bs[kk][tx * 4];
#pragma unroll
        for (int i = 0; i < 8; ++i) {
            ull a = As2[kk][ty * 8 + i];
            fma2(acc[i][0], a, bb.x);
            fma2(acc[i][1], a, bb.y);
        }
    }
#pragma unroll
    for (int i = 0; i < 8; ++i) {
        ulonglong2 s; s.x = acc[i][0]; s.y = acc[i][1];
        *(ulonglong2*)&C[(size_t)(m0 + ty * 8 + i) * 256 + q0 + tx * 4] = s;
    }
}

// ===================== softmax over q ==============================
__global__ void __launch_bounds__(256) softmax_k() {
    int w = threadIdx.x >> 5, lane = threadIdx.x & 31;
    size_t r = (size_t)blockIdx.x * 8 + w;              // < 51200
    float* row = g_pT + r * 256;
    float v[8];
    float mx = -1e30f;
#pragma unroll
    for (int i = 0; i < 8; ++i) { v[i] = row[lane + i * 32]; mx = fmaxf(mx, v[i]); }
#pragma unroll
    for (int o = 16; o > 0; o >>= 1) mx = fmaxf(mx, __shfl_xor_sync(0xffffffffu, mx, o));
    float s = 0.f;
#pragma unroll
    for (int i = 0; i < 8; ++i) { v[i] = __expf(v[i] - mx); s += v[i]; }
#pragma unroll
    for (int o = 16; o > 0; o >>= 1) s += __shfl_xor_sync(0xffffffffu, s, o);
    float inv = 1.f / s;
#pragma unroll
    for (int i = 0; i < 8; ++i) row[lane + i * 32] = v[i] * inv;
}

// ====== vt (FFMA2): C[c][t] += valtC[c][k]*pT[t,k], splitK=10 ======
// grid (4, 100): t0=bx*64, by = kg*10+fi
__global__ void __launch_bounds__(256) k_vt() {
    int t0 = blockIdx.x * 64;
    int z = blockIdx.y, fi = z % 10, kg = z / 10;
    const float* Bp = g_pT + (size_t)fi * 1310720;
    float* Cp = g_vtpart + (size_t)z * 32768;
    __shared__ ull As2[16][132];
    __shared__ __align__(16) float Bs[16][64];
    int tid = threadIdx.x, tx = tid & 15, ty = tid >> 4;
    ull acc[8][2] = {};

    int kbase = kg * 512;
    for (int k0 = kbase; k0 < kbase + 512; k0 += 16) {
        __syncthreads();
        {
            int rr = tid >> 1;
#pragma unroll
            for (int e0 = 0; e0 < 2; ++e0) {
                int ko = (tid & 1) * 4 + e0 * 8;
                float4 av = *(const float4*)&g_valtC[(size_t)rr * 5120 + k0 + ko];
                As2[ko + 0][rr] = pk2(av.x, av.x);
                As2[ko + 1][rr] = pk2(av.y, av.y);
                As2[ko + 2][rr] = pk2(av.z, av.z);
                As2[ko + 3][rr] = pk2(av.w, av.w);
            }
        }
        {
            int nblk = k0 >> 8, a0 = k0 & 255;
            const float* Bn = Bp + (size_t)nblk * 65536 + a0;
            int tt = tid >> 2, kk0 = (tid & 3) * 4;
            float4 bv = *(const float4*)&Bn[(size_t)(t0 + tt) * 256 + kk0];
            Bs[kk0 + 0][tt] = bv.x; Bs[kk0 + 1][tt] = bv.y;
            Bs[kk0 + 2][tt] = bv.z; Bs[kk0 + 3][tt] = bv.w;
        }
        __syncthreads();
#pragma unroll
        for (int kk = 0; kk < 16; ++kk) {
            ulonglong2 bb = *(const ulonglong2*)&Bs[kk][tx * 4];
#pragma unroll
            for (int i = 0; i < 8; ++i) {
                ull a = As2[kk][ty * 8 + i];
                fma2(acc[i][0], a, bb.x);
                fma2(acc[i][1], a, bb.y);
            }
        }
    }
#pragma unroll
    for (int i = 0; i < 8; ++i) {
        ulonglong2 s; s.x = acc[i][0]; s.y = acc[i][1];
        *(ulonglong2*)&Cp[(size_t)(ty * 8 + i) * 256 + t0 + tx * 4] = s;
    }
}

__global__ void __launch_bounds__(256) vt_reduce() {
    int idx = blockIdx.x * 256 + threadIdx.x;          // < 327680
    int fi = idx >> 15, r = idx & 32767;
    float s = 0.f;
#pragma unroll
    for (int kg = 0; kg < 10; ++kg) s += g_vtpart[((size_t)(kg * 10 + fi) << 15) + r];
    int c = r >> 8, t = r & 255;
    g_final[((size_t)fi * 256 + 128 + c) * 256 + t] = s;
}

// ============ h = W2sT * final (FFMA2, 128x64 tiles) ===============
// grid (2, 4, 10)
__global__ void __launch_bounds__(256) k_h() {
    int z = blockIdx.z;
    const float* A = g_W2sT + (size_t)(z >> 1) * 65536;
    const float* B = g_final + (size_t)z * 65536;
    float* C = g_h + (size_t)z * 65536;
    int m0 = blockIdx.x * 128, n0 = blockIdx.y * 64;
    __shared__ ull As2[16][132];
    __shared__ __align__(16) float Bs[16][64];
    int tid = threadIdx.x, tx = tid & 15, ty = tid >> 4;
    ull acc[8][2] = {};

    for (int k0 = 0; k0 < 256; k0 += 16) {
        __syncthreads();
        {
            int rr = tid >> 1;
#pragma unroll
            for (int e0 = 0; e0 < 2; ++e0) {
                int ko = (tid & 1) * 4 + e0 * 8;
                float4 av = *(const float4*)&A[(size_t)(m0 + rr) * 256 + k0 + ko];
                As2[ko + 0][rr] = pk2(av.x, av.x);
                As2[ko + 1][rr] = pk2(av.y, av.y);
                As2[ko + 2][rr] = pk2(av.z, av.z);
                As2[ko + 3][rr] = pk2(av.w, av.w);
            }
        }
        {
            int nn = tid & 63, kk = tid >> 6;           // 4 kk per pass
#pragma unroll
            for (int e0 = 0; e0 < 4; ++e0)
                Bs[kk + e0 * 4][nn] = B[(size_t)(k0 + kk + e0 * 4) * 256 + n0 + nn];
        }
        __syncthreads();
#pragma unroll
        for (int kk = 0; kk < 16; ++kk) {
            ulonglong2 bb = *(const ulonglong2*)&Bs[kk][tx * 4];
#pragma unroll
            for (int i = 0; i < 8; ++i) {
                ull a = As2[kk][ty * 8 + i];
                fma2(acc[i][0], a, bb.x);
                fma2(acc[i][1], a, bb.y);
            }
        }
    }
#pragma unroll
    for (int i = 0; i < 8; ++i) {
        ulonglong2 s; s.x = acc[i][0]; s.y = acc[i][1];
        *(ulonglong2*)&C[(size_t)(m0 + ty * 8 + i) * 256 + n0 + tx * 4] = s;
    }
}

// == part1 (FFMA2, fused levels): out = W1*feat + up16(h) + cbias ===
// grid (2, 86, 2): y decodes (lvl, n-tile)
__global__ void __launch_bounds__(256) k_part1(const float* __restrict__ cw,
                                               FeatPtrs fp, float* __restrict__ out) {
    int yb = blockIdx.y;
    int lvl = 0;
    while (yb >= c_ppre[lvl + 1]) ++lvl;
    int n0 = (yb - c_ppre[lvl]) * 64;
    int N = c_N[lvl], lgW = c_lg[lvl], toff = d_TOFF[lvl];
    int m0 = blockIdx.x * 128, b = blockIdx.z;
    const float* Bb = fp.p[lvl] + (size_t)b * 256 * N;
    float* Cb = out + (size_t)c_outoff[lvl] + (size_t)b * 256 * N;
    int img = lvl * 2 + b;
    __shared__ ull As2[16][132];
    __shared__ __align__(16) float Bs[16][64];
    int tid = threadIdx.x, tx = tid & 15, ty = tid >> 4;
    ull acc[8][2] = {};

    for (int k0 = 0; k0 < 256; k0 += 16) {
        __syncthreads();
        {
            int rr = tid >> 1;
#pragma unroll
            for (int e0 = 0; e0 < 2; ++e0) {
                int ko = (tid & 1) * 4 + e0 * 8;
                float4 av = *(const float4*)&cw[(size_t)(m0 + rr) * 512 + k0 + ko];
                As2[ko + 0][rr] = pk2(av.x, av.x);
                As2[ko + 1][rr] = pk2(av.y, av.y);
                As2[ko + 2][rr] = pk2(av.z, av.z);
                As2[ko + 3][rr] = pk2(av.w, av.w);
            }
        }
        {
            int nn = tid & 63, kk = tid >> 6;
#pragma unroll
            for (int e0 = 0; e0 < 4; ++e0) {
                int p = n0 + nn;
                float bv = 0.f;
                if (p < N) bv = Bb[(size_t)(k0 + kk + e0 * 4) * N + p];
                Bs[kk + e0 * 4][nn] = bv;
            }
        }
        __syncthreads();
#pragma unroll
        for (int kk = 0; kk < 16; ++kk) {
            ulonglong2 bb = *(const ulonglong2*)&Bs[kk][tx * 4];
#pragma unroll
            for (int i = 0; i < 8; ++i) {
                ull a = As2[kk][ty * 8 + i];
                fma2(acc[i][0], a, bb.x);
                fma2(acc[i][1], a, bb.y);
            }
        }
    }

    int Wm = (1 << lgW) - 1;
#pragma unroll
    for (int i = 0; i < 8; ++i) {
        int oc = m0 + ty * 8 + i;
        float cbv = g_cbias[lvl * 256 + oc];
        const float* hrow = g_h + ((size_t)img * 256 + oc) * 256;
        float2 f0 = up2(acc[i][0]), f1 = up2(acc[i][1]);
        float av[4] = {f0.x, f0.y, f1.x, f1.y};
#pragma unroll
        for (int j = 0; j < 4; ++j) {
            int p = n0 + tx * 4 + j;
            if (p < N) {
                int yy = p >> lgW, xx = p & Wm;
                int y0 = g_ui0[toff + yy], y1 = g_ui1[toff + yy];
                int x0 = g_ui0[toff + xx], x1 = g_ui1[toff + xx];
                float wy = g_uw[toff + yy], wx = g_uw[toff + xx];
                float v00 = hrow[y0 * 16 + x0], v01 = hrow[y0 * 16 + x1];
                float v10 = hrow[y1 * 16 + x0], v11 = hrow[y1 * 16 + x1];
                float top = v00 * (1.f - wx) + v01 * wx;
                float bot = v10 * (1.f - wx) + v11 * wx;
                Cb[(size_t)oc * N + p] = av[j] + top * (1.f - wy) + bot * wy + cbv;
            }
        }
    }
}

// ===================== attention upsample (float4) =================
__global__ void __launch_bounds__(256) attn_k(float* __restrict__ out,
                                              int lvl, int lg, int toff) {
    int H = 1 << lg;
    int t = blockIdx.x, bn = blockIdx.y;
    int b = bn / 20, n = bn - b * 20;
    int img = lvl * 2 + b;
    const float* row = g_pT + ((size_t)((img * 20 + n) * 256 + t)) * 256;
    __shared__ float sr[256];
    __shared__ int sy0[64], sy1[64];
    __shared__ float swy[64];
    int tid = threadIdx.x;
    sr[tid] = row[tid];
    if (tid < H) { sy0[tid] = g_ui0[toff + tid]; sy1[tid] = g_ui1[toff + tid]; swy[tid] = g_uw[toff + tid]; }
    __syncthreads();
    float* ob = out + ((size_t)bn * 256 + t) * H * H;
    for (int p = tid * 4; p < H * H; p += 1024) {
        int y = p >> lg, xb = p & (H - 1);
        int y0 = sy0[y], y1 = sy1[y];
        float wy = swy[y], cwy = 1.f - wy;
        float r[4];
#pragma unroll
        for (int j = 0; j < 4; ++j) {
            int x = xb + j;
            int x0 = sy0[x], x1 = sy1[x];
            float wx = swy[x];
            float v00 = sr[y0 * 16 + x0], v01 = sr[y0 * 16 + x1];
            float v10 = sr[y1 * 16 + x0], v11 = sr[y1 * 16 + x1];
            float top = v00 * (1.f - wx) + v01 * wx;
            float bot = v10 * (1.f - wx) + v11 * wx;
            r[j] = top * cwy + bot * wy;
        }
        *(float4*)&ob[p] = make_float4(r[0], r[1], r[2], r[3]);
    }
}

// ============================ launch ===============================
extern "C" void kernel_launch(void* const* d_in, const int* in_sizes, int n_in,
                              void* d_out, int out_size) {
    const float* feat[5];
    for (int i = 0; i < 5; ++i) feat[i] = (const float*)d_in[i];
    const float* att = (const float*)d_in[5];
    const float* cw  = (const float*)d_in[18];
    float* out = (float*)d_out;

    static const int lgs[5]    = {6, 5, 4, 3, 2};
    static const int toffs[5]  = {0, 64, 96, 112, 120};
    static const int attoff[5] = {2793472, 44736512, 55222272, 57843712, 58499072};

    FeatPtrs fp;
    for (int i = 0; i < 5; ++i) fp.p[i] = feat[i];

    k_prep<<<12486, 256>>>(fp,
        (const float*)d_in[6],  (const float*)d_in[7],
        (const float*)d_in[8],  (const float*)d_in[9],
        (const float*)d_in[10], (const float*)d_in[11],
        (const float*)d_in[12], (const float*)d_in[13],
        (const float*)d_in[14], (const float*)d_in[15],
        (const float*)d_in[16], (const float*)d_in[17],
        cw, (const float*)d_in[19]);
    conv16<<<dim3(30, 10, 2), 256>>>(att);
    reduce_all<<<4800, 256>>>();
    k_logits<<<dim3(40, 4, 10), 256>>>();
    softmax_k<<<6400, 256>>>();
    k_vt<<<dim3(4, 100), 256>>>();
    vt_reduce<<<1280, 256>>>();
    k_h<<<dim3(2, 4, 10), 256>>>();
    k_part1<<<dim3(2, 86, 2), 256>>>(cw, fp, out);
    for (int l = 0; l < 5; ++l)
        attn_k<<<dim3(256, 40), 256>>>(out + attoff[l], l, lgs[l], toffs[l]);
}

// round 7
// speedup vs baseline: 1.3230x; 1.0015x over previous
#include <cuda_runtime.h>
#include <math.h>

typedef unsigned long long ull;

__device__ __forceinline__ ull pk2(float lo, float hi) {
    ull r; asm("mov.b64 %0, {%1, %2};" : "=l"(r) : "f"(lo), "f"(hi)); return r;
}
__device__ __forceinline__ void fma2(ull& d, ull a, ull b) {
    asm("fma.rn.f32x2 %0, %1, %2, %3;" : "=l"(d) : "l"(a), "l"(b), "l"(d));
}
__device__ __forceinline__ float2 up2(ull v) {
    float2 f; asm("mov.b64 {%0, %1}, %2;" : "=f"(f.x), "=f"(f.y) : "l"(v)); return f;
}

// ============================ constants ============================
__constant__ int d_H[5]    = {64, 32, 16, 8, 4};
__constant__ int d_TOFF[5] = {0, 64, 96, 112, 120};
__constant__ int c_ppre[6]   = {0, 64, 80, 84, 85, 86};     // part1 tile prefix
__constant__ int c_N[5]      = {4096, 1024, 256, 64, 16};
__constant__ int c_lg[5]     = {6, 5, 4, 3, 2};
__constant__ int c_outoff[5] = {0, 2097152, 2621440, 2752512, 2785280};

// ============================ scratch ==============================
__device__ float g_fs[655360];        // [fi(10)][cin 256][q 256]
__device__ float g_part[2457600];     // conv partials [cg 2][img 30][oc 160][pix 256]
__device__ float g_keytT[163840];     // [n][t][k]  (n 20, t 256, k 32)
__device__ float g_valtC[655360];     // [c 128][k 5120]
__device__ float g_kq[81920];         // [fi][k 32][q 256]
__device__ float g_final[655360];     // [fi][i 256][q 256]
__device__ float g_pT[13107200];      // [fi][n][t][q]
__device__ float g_vtpart[3276800];   // [z=kg*10+fi][c 128][t 256]
__device__ float g_h[655360];         // [fi][oc 256][q 256]
__device__ float g_W2sT[327680];      // [lvl][oc][i]
__device__ float g_cbias[1280];       // [lvl][oc]
__device__ float g_wAtt[368640];      // [oc 160][cin 256][9]
__device__ float g_bAtt[160];
__device__ float g_wF[1843200];       // [lvl][oc 160][cin 256][9]
__device__ float g_bF[800];
__device__ int   g_fi0[80], g_fi1[80];
__device__ float g_fw[80];            // H->16 tables
__device__ int   g_ui0[124], g_ui1[124];
__device__ float g_uw[124];           // 16->H tables

struct FeatPtrs { const float* p[5]; };

// ================== merged prep (1 launch) =========================
// bx ranges: [0,7200) wcat_feat | [7200,8640) wcat_att | [8640,9920) w2s
//            [9920,12480) fs    | [12480,12485) cbias  | 12485 tables
__global__ void __launch_bounds__(256) k_prep(
    FeatPtrs fp,
    const float* __restrict__ ktw, const float* __restrict__ ktb,
    const float* __restrict__ vtw, const float* __restrict__ vtb,
    const float* __restrict__ kqw, const float* __restrict__ kqb,
    const float* __restrict__ vqw, const float* __restrict__ vqb,
    const float* __restrict__ bng, const float* __restrict__ bnb,
    const float* __restrict__ bnm, const float* __restrict__ bnv,
    const float* __restrict__ cw,  const float* __restrict__ cb) {
    int bx = blockIdx.x, tid = threadIdx.x;
    if (bx < 7200) {                                   // wcat_feat
        int idx = bx * 256 + tid;
        if (idx < 1843200) {
            int lvl = idx / 368640, r2 = idx % 368640;
            int oc = r2 / 2304, r = r2 % 2304;
            g_wF[idx] = (oc < 32) ? kqw[(lvl * 32 + oc) * 2304 + r]
                                  : vqw[(lvl * 128 + oc - 32) * 2304 + r];
        }
        if (idx < 800) {
            int lvl = idx / 160, oc = idx % 160;
            g_bF[idx] = (oc < 32) ? kqb[lvl * 32 + oc] : vqb[lvl * 128 + oc - 32];
        }
    } else if (bx < 8640) {                            // wcat_att
        int idx = (bx - 7200) * 256 + tid;
        if (idx < 368640) {
            int oc = idx / 2304, r = idx % 2304;
            g_wAtt[idx] = (oc < 32) ? ktw[oc * 2304 + r] : vtw[(oc - 32) * 2304 + r];
        }
        if (idx < 160) g_bAtt[idx] = (idx < 32) ? ktb[idx] : vtb[idx - 32];
    } else if (bx < 9920) {                            // w2s
        int idx = (bx - 8640) * 256 + tid;
        int lvl = idx >> 16, r = idx & 65535, oc = r >> 8, i = r & 255;
        float sc = bng[lvl * 256 + i] / sqrtf(bnv[lvl * 256 + i] + 1e-5f);
        g_W2sT[idx] = cw[oc * 512 + 256 + i] * sc;
    } else if (bx < 12480) {                           // fs (needs tables: inline compute)
        int idx = (bx - 9920) * 256 + tid;             // < 655360
        int q = idx & 255, c = (idx >> 8) & 255, img = idx >> 16;
        int lvl = img >> 1, b = img & 1;
        int H = d_H[lvl];
        float r = (float)((double)(H - 1) / 15.0);
        int yq = q >> 4, xq = q & 15;
        float sy = yq * r, sx = xq * r;
        int y0 = min((int)floorf(sy), H - 1), x0 = min((int)floorf(sx), H - 1);
        int y1 = min(y0 + 1, H - 1), x1 = min(x0 + 1, H - 1);
        float wy = sy - y0, wx = sx - x0;
        const float* src = fp.p[lvl] + ((size_t)(b * 256 + c)) * H * H;
        float v00 = src[y0 * H + x0], v01 = src[y0 * H + x1];
        float v10 = src[y1 * H + x0], v11 = src[y1 * H + x1];
        float top = v00 * (1.f - wx) + v01 * wx;
        float bot = v10 * (1.f - wx) + v11 * wx;
        g_fs[idx] = top * (1.f - wy) + bot * wy;
    } else if (bx < 12485) {                           // cbias
        int lvl = bx - 12480, oc = tid;
        float s = 0.f;
        for (int i = 0; i < 256; ++i) {
            float sc = bng[lvl * 256 + i] / sqrtf(bnv[lvl * 256 + i] + 1e-5f);
            s += cw[oc * 512 + 256 + i] * (bnb[lvl * 256 + i] - sc * bnm[lvl * 256 + i]);
        }
        g_cbias[lvl * 256 + oc] = cb[oc] + s;
    } else {                                           // tables
        if (tid < 80) {
            int lvl = tid >> 4, o = tid & 15;
            int H = d_H[lvl];
            float r = (float)((double)(H - 1) / 15.0);
            float s = (float)o * r;
            int i0 = min((int)floorf(s), H - 1);
            int i1 = min(i0 + 1, H - 1);
            g_fi0[tid] = i0; g_fi1[tid] = i1; g_fw[tid] = s - (float)i0;
        }
        if (tid >= 128 && tid < 252) {
            int j = tid - 128;
            int lvl = (j < 64) ? 0 : (j < 96) ? 1 : (j < 112) ? 2 : (j < 120) ? 3 : 4;
            int o = j - d_TOFF[lvl];
            int H = d_H[lvl];
            float r = (float)(15.0 / (double)(H - 1));
            float s = (float)o * r;
            int i0 = min((int)floorf(s), 15);
            int i1 = min(i0 + 1, 15);
            g_ui0[j] = i0; g_ui1[j] = i1; g_uw[j] = s - (float)i0;
        }
    }
}

// ===== 3x3 SAME conv on 16x16 (FFMA2), att(20)+feat(10) imgs =======
// grid (30, 10, 2): x=img, y=16-oc group, z=128-cin group
__global__ void __launch_bounds__(256) conv16(const float* __restrict__ att) {
    int img = blockIdx.x, grp = blockIdx.y, cg = blockIdx.z;
    const float* inp; const float* wb;
    if (img < 20) {
        inp = att + (size_t)img * 65536 + (size_t)cg * 32768;
        wb  = g_wAtt + (size_t)grp * 16 * 2304 + (size_t)cg * 1152;
    } else {
        int fi = img - 20;
        inp = g_fs + (size_t)fi * 65536 + (size_t)cg * 32768;
        wb  = g_wF + (size_t)(fi >> 1) * 368640 + (size_t)grp * 16 * 2304 + (size_t)cg * 1152;
    }
    float* outp = g_part + (((size_t)cg * 30 + img) * 160 + grp * 16) * 256;

    __shared__ float tile[8][18][18];
    __shared__ __align__(16) float wsh[8][9][16];
    int tid = threadIdx.x;
    for (int i = tid; i < 8 * 18 * 18; i += 256) ((float*)tile)[i] = 0.f;

    ull acc[8] = {};
    int y = tid >> 4, x = tid & 15;

    for (int cc = 0; cc < 128; cc += 8) {
        __syncthreads();
#pragma unroll
        for (int i = 0; i < 8; ++i) {
            int idx = tid + i * 256;
            int c = idx >> 8, p = idx & 255;
            tile[c][(p >> 4) + 1][(p & 15) + 1] = inp[(cc + c) * 256 + p];
        }
#pragma unroll
        for (int i = 0; i < 5; ++i) {
            int idx = tid + i * 256;
            if (idx < 1152) {
                int c = idx / 144, r = idx % 144;
                int tap = r / 16, oc = r % 16;
                wsh[c][tap][oc] = wb[(size_t)oc * 2304 + (cc + c) * 9 + tap];
            }
        }
        __syncthreads();
#pragma unroll
        for (int c = 0; c < 8; ++c) {
            float v[9];
#pragma unroll
            for (int dy = 0; dy < 3; ++dy)
#pragma unroll
                for (int dx = 0; dx < 3; ++dx)
                    v[dy * 3 + dx] = tile[c][y + dy][x + dx];
#pragma unroll
            for (int tap = 0; tap < 9; ++tap) {
                ull vv = pk2(v[tap], v[tap]);
                const ulonglong2* wp = (const ulonglong2*)&wsh[c][tap][0];
#pragma unroll
                for (int j = 0; j < 4; ++j) {
                    ulonglong2 w2 = wp[j];
                    fma2(acc[2 * j], vv, w2.x);
                    fma2(acc[2 * j + 1], vv, w2.y);
                }
            }
        }
    }
#pragma unroll
    for (int j = 0; j < 8; ++j) {
        float2 f = up2(acc[j]);
        outp[(2 * j) * 256 + tid]     = f.x;
        outp[(2 * j + 1) * 256 + tid] = f.y;
    }
}

// ================ merged partial reduction + layout ================
__global__ void __launch_bounds__(256) reduce_all() {
    int idx = blockIdx.x * 256 + threadIdx.x;          // < 1228800
    int img = idx / 40960, r = idx % 40960;
    int oc = r >> 8, pix = r & 255;
    float s = g_part[idx] + g_part[1228800 + idx];
    if (img < 20) {
        s += g_bAtt[oc];
        if (oc < 32) g_keytT[((size_t)img * 256 + pix) * 32 + oc] = s;
        else         g_valtC[((size_t)(oc - 32) * 20 + img) * 256 + pix] = s;
    } else {
        int fi = img - 20, lvl = fi >> 1;
        s += g_bF[lvl * 160 + oc];
        if (oc < 32) g_kq[((size_t)fi * 32 + oc) * 256 + pix] = s;
        else         g_final[((size_t)fi * 256 + (oc - 32)) * 256 + pix] = 20.f * s;
    }
}

// ============ logits (FFMA2): pT[nt][q] = keytT[nt][k]*kq[k][q] ====
// grid (40, 4, 10): m0=bx*128, q0=by*64, z=fi. K=32 single tile.
__global__ void __launch_bounds__(256) k_logits() {
    int m0 = blockIdx.x * 128, q0 = blockIdx.y * 64;
    int fi = blockIdx.z;
    const float* B = g_kq + (size_t)fi * 8192;
    float* C = g_pT + (size_t)fi * 1310720;
    __shared__ ull As2[32][132];
    __shared__ __align__(16) float Bs[32][64];
    int tid = threadIdx.x, tx = tid & 15, ty = tid >> 4;

#pragma unroll
    for (int i = 0; i < 4; ++i) {                       // A: 128x32 dup-pairs
        int u = tid + i * 256;
        int rr = u >> 3, ko = (u & 7) * 4;
        float4 av = *(const float4*)&g_keytT[(size_t)(m0 + rr) * 32 + ko];
        As2[ko + 0][rr] = pk2(av.x, av.x);
        As2[ko + 1][rr] = pk2(av.y, av.y);
        As2[ko + 2][rr] = pk2(av.z, av.z);
        As2[ko + 3][rr] = pk2(av.w, av.w);
    }
#pragma unroll
    for (int i = 0; i < 8; ++i) {                       // B: 32x64
        int e = tid + i * 256;
        int n = e & 63, kk = e >> 6;
        Bs[kk][n] = B[(size_t)kk * 256 + q0 + n];
    }
    __syncthreads();

    ull acc[8][2] = {};
#pragma unroll
    for (int kk = 0; kk < 32; ++kk) {
        ulonglong2 bb = *(const ulonglong2*)&Bs[kk][tx * 4];
#pragma unroll
        for (int i = 0; i < 8; ++i) {
            ull a = As2[kk][ty * 8 + i];
            fma2(acc[i][0], a, bb.x);
            fma2(acc[i][1], a, bb.y);
        }
    }
#pragma unroll
    for (int i = 0; i < 8; ++i) {
        ulonglong2 s; s.x = acc[i][0]; s.y = acc[i][1];
        *(ulonglong2*)&C[(size_t)(m0 + ty * 8 + i) * 256 + q0 + tx * 4] = s;
    }
}

// ===================== softmax over q ==============================
__global__ void __launch_bounds__(256) softmax_k() {
    int w = threadIdx.x >> 5, lane = threadIdx.x & 31;
    size_t r = (size_t)blockIdx.x * 8 + w;              // < 51200
    float* row = g_pT + r * 256;
    float v[8];
    float mx = -1e30f;
#pragma unroll
    for (int i = 0; i < 8; ++i) { v[i] = row[lane + i * 32]; mx = fmaxf(mx, v[i]); }
#pragma unroll
    for (int o = 16; o > 0; o >>= 1) mx = fmaxf(mx, __shfl_xor_sync(0xffffffffu, mx, o));
    float s = 0.f;
#pragma unroll
    for (int i = 0; i < 8; ++i) { v[i] = __expf(v[i] - mx); s += v[i]; }
#pragma unroll
    for (int o = 16; o > 0; o >>= 1) s += __shfl_xor_sync(0xffffffffu, s, o);
    float inv = 1.f / s;
#pragma unroll
    for (int i = 0; i < 8; ++i) row[lane + i * 32] = v[i] * inv;
}

// ====== vt (FFMA2): C[c][t] += valtC[c][k]*pT[t,k], splitK=10 ======
// grid (4, 100): t0=bx*64, by = kg*10+fi
__global__ void __launch_bounds__(256) k_vt() {
    int t0 = blockIdx.x * 64;
    int z = blockIdx.y, fi = z % 10, kg = z / 10;
    const float* Bp = g_pT + (size_t)fi * 1310720;
    float* Cp = g_vtpart + (size_t)z * 32768;
    __shared__ ull As2[16][132];
    __shared__ __align__(16) float Bs[16][64];
    int tid = threadIdx.x, tx = tid & 15, ty = tid >> 4;
    ull acc[8][2] = {};

    int kbase = kg * 512;
    for (int k0 = kbase; k0 < kbase + 512; k0 += 16) {
        __syncthreads();
        {
            int rr = tid >> 1;
#pragma unroll
            for (int e0 = 0; e0 < 2; ++e0) {
                int ko = (tid & 1) * 4 + e0 * 8;
                float4 av = *(const float4*)&g_valtC[(size_t)rr * 5120 + k0 + ko];
                As2[ko + 0][rr] = pk2(av.x, av.x);
                As2[ko + 1][rr] = pk2(av.y, av.y);
                As2[ko + 2][rr] = pk2(av.z, av.z);
                As2[ko + 3][rr] = pk2(av.w, av.w);
            }
        }
        {
            int nblk = k0 >> 8, a0 = k0 & 255;
            const float* Bn = Bp + (size_t)nblk * 65536 + a0;
            int tt = tid >> 2, kk0 = (tid & 3) * 4;
            float4 bv = *(const float4*)&Bn[(size_t)(t0 + tt) * 256 + kk0];
            Bs[kk0 + 0][tt] = bv.x; Bs[kk0 + 1][tt] = bv.y;
            Bs[kk0 + 2][tt] = bv.z; Bs[kk0 + 3][tt] = bv.w;
        }
        __syncthreads();
#pragma unroll
        for (int kk = 0; kk < 16; ++kk) {
            ulonglong2 bb = *(const ulonglong2*)&Bs[kk][tx * 4];
#pragma unroll
            for (int i = 0; i < 8; ++i) {
                ull a = As2[kk][ty * 8 + i];
                fma2(acc[i][0], a, bb.x);
                fma2(acc[i][1], a, bb.y);
            }
        }
    }
#pragma unroll
    for (int i = 0; i < 8; ++i) {
        ulonglong2 s; s.x = acc[i][0]; s.y = acc[i][1];
        *(ulonglong2*)&Cp[(size_t)(ty * 8 + i) * 256 + t0 + tx * 4] = s;
    }
}

__global__ void __launch_bounds__(256) vt_reduce() {
    int idx = blockIdx.x * 256 + threadIdx.x;          // < 327680
    int fi = idx >> 15, r = idx & 32767;
    float s = 0.f;
#pragma unroll
    for (int kg = 0; kg < 10; ++kg) s += g_vtpart[((size_t)(kg * 10 + fi) << 15) + r];
    int c = r >> 8, t = r & 255;
    g_final[((size_t)fi * 256 + 128 + c) * 256 + t] = s;
}

// ============ h = W2sT * final (FFMA2, 128x64 tiles) ===============
// grid (2, 4, 10)
__global__ void __launch_bounds__(256) k_h() {
    int z = blockIdx.z;
    const float* A = g_W2sT + (size_t)(z >> 1) * 65536;
    const float* B = g_final + (size_t)z * 65536;
    float* C = g_h + (size_t)z * 65536;
    int m0 = blockIdx.x * 128, n0 = blockIdx.y * 64;
    __shared__ ull As2[16][132];
    __shared__ __align__(16) float Bs[16][64];
    int tid = threadIdx.x, tx = tid & 15, ty = tid >> 4;
    ull acc[8][2] = {};

    for (int k0 = 0; k0 < 256; k0 += 16) {
        __syncthreads();
        {
            int rr = tid >> 1;
#pragma unroll
            for (int e0 = 0; e0 < 2; ++e0) {
                int ko = (tid & 1) * 4 + e0 * 8;
                float4 av = *(const float4*)&A[(size_t)(m0 + rr) * 256 + k0 + ko];
                As2[ko + 0][rr] = pk2(av.x, av.x);
                As2[ko + 1][rr] = pk2(av.y, av.y);
                As2[ko + 2][rr] = pk2(av.z, av.z);
                As2[ko + 3][rr] = pk2(av.w, av.w);
            }
        }
        {
            int nn = tid & 63, kk = tid >> 6;           // 4 kk per pass
#pragma unroll
            for (int e0 = 0; e0 < 4; ++e0)
                Bs[kk + e0 * 4][nn] = B[(size_t)(k0 + kk + e0 * 4) * 256 + n0 + nn];
        }
        __syncthreads();
#pragma unroll
        for (int kk = 0; kk < 16; ++kk) {
            ulonglong2 bb = *(const ulonglong2*)&Bs[kk][tx * 4];
#pragma unroll
            for (int i = 0; i < 8; ++i) {
                ull a = As2[kk][ty * 8 + i];
                fma2(acc[i][0], a, bb.x);
                fma2(acc[i][1], a, bb.y);
            }
        }
    }
#pragma unroll
    for (int i = 0; i < 8; ++i) {
        ulonglong2 s; s.x = acc[i][0]; s.y = acc[i][1];
        *(ulonglong2*)&C[(size_t)(m0 + ty * 8 + i) * 256 + n0 + tx * 4] = s;
    }
}

// == part1 (FFMA2, fused levels): out = W1*feat + up16(h) + cbias ===
// grid (2, 86, 2): y decodes (lvl, n-tile)
__global__ void __launch_bounds__(256) k_part1(const float* __restrict__ cw,
                                               FeatPtrs fp, float* __restrict__ out) {
    int yb = blockIdx.y;
    int lvl = 0;
    while (yb >= c_ppre[lvl + 1]) ++lvl;
    int n0 = (yb - c_ppre[lvl]) * 64;
    int N = c_N[lvl], lgW = c_lg[lvl], toff = d_TOFF[lvl];
    int m0 = blockIdx.x * 128, b = blockIdx.z;
    const float* Bb = fp.p[lvl] + (size_t)b * 256 * N;
    float* Cb = out + (size_t)c_outoff[lvl] + (size_t)b * 256 * N;
    int img = lvl * 2 + b;
    __shared__ ull As2[16][132];
    __shared__ __align__(16) float Bs[16][64];
    int tid = threadIdx.x, tx = tid & 15, ty = tid >> 4;
    ull acc[8][2] = {};

    for (int k0 = 0; k0 < 256; k0 += 16) {
        __syncthreads();
        {
            int rr = tid >> 1;
#pragma unroll
            for (int e0 = 0; e0 < 2; ++e0) {
                int ko = (tid & 1) * 4 + e0 * 8;
                float4 av = *(const float4*)&cw[(size_t)(m0 + rr) * 512 + k0 + ko];
                As2[ko + 0][rr] = pk2(av.x, av.x);
                As2[ko + 1][rr] = pk2(av.y, av.y);
                As2[ko + 2][rr] = pk2(av.z, av.z);
                As2[ko + 3][rr] = pk2(av.w, av.w);
            }
        }
        {
            int nn = tid & 63, kk = tid >> 6;
#pragma unroll
            for (int e0 = 0; e0 < 4; ++e0) {
                int p = n0 + nn;
                float bv = 0.f;
                if (p < N) bv = Bb[(size_t)(k0 + kk + e0 * 4) * N + p];
                Bs[kk + e0 * 4][nn] = bv;
            }
        }
        __syncthreads();
#pragma unroll
        for (int kk = 0; kk < 16; ++kk) {
            ulonglong2 bb = *(const ulonglong2*)&Bs[kk][tx * 4];
#pragma unroll
            for (int i = 0; i < 8; ++i) {
                ull a = As2[kk][ty * 8 + i];
                fma2(acc[i][0], a, bb.x);
                fma2(acc[i][1], a, bb.y);
            }
        }
    }

    int Wm = (1 << lgW) - 1;
#pragma unroll
    for (int i = 0; i < 8; ++i) {
        int oc = m0 + ty * 8 + i;
        float cbv = g_cbias[lvl * 256 + oc];
        const float* hrow = g_h + ((size_t)img * 256 + oc) * 256;
        float2 f0 = up2(acc[i][0]), f1 = up2(acc[i][1]);
        float av[4] = {f0.x, f0.y, f1.x, f1.y};
#pragma unroll
        for (int j = 0; j < 4; ++j) {
            int p = n0 + tx * 4 + j;
            if (p < N) {
                int yy = p >> lgW, xx = p & Wm;
                int y0 = g_ui0[toff + yy], y1 = g_ui1[toff + yy];
                int x0 = g_ui0[toff + xx], x1 = g_ui1[toff + xx];
                float wy = g_uw[toff + yy], wx = g_uw[toff + xx];
                float v00 = hrow[y0 * 16 + x0], v01 = hrow[y0 * 16 + x1];
                float v10 = hrow[y1 * 16 + x0], v11 = hrow[y1 * 16 + x1];
                float top = v00 * (1.f - wx) + v01 * wx;
                float bot = v10 * (1.f - wx) + v11 * wx;
                Cb[(size_t)oc * N + p] = av[j] + top * (1.f - wy) + bot * wy + cbv;
            }
        }
    }
}

// ===================== attention upsample (float4) =================
__global__ void __launch_bounds__(256) attn_k(float* __restrict__ out,
                                              int lvl, int lg, int toff) {
    int H = 1 << lg;
    int t = blockIdx.x, bn = blockIdx.y;
    int b = bn / 20, n = bn - b * 20;
    int img = lvl * 2 + b;
    const float* row = g_pT + ((size_t)((img * 20 + n) * 256 + t)) * 256;
    __shared__ float sr[256];
    __shared__ int sy0[64], sy1[64];
    __shared__ float swy[64];
    int tid = threadIdx.x;
    sr[tid] = row[tid];
    if (tid < H) { sy0[tid] = g_ui0[toff + tid]; sy1[tid] = g_ui1[toff + tid]; swy[tid] = g_uw[toff + tid]; }
    __syncthreads();
    float* ob = out + ((size_t)bn * 256 + t) * H * H;
    for (int p = tid * 4; p < H * H; p += 1024) {
        int y = p >> lg, xb = p & (H - 1);
        int y0 = sy0[y], y1 = sy1[y];
        float wy = swy[y], cwy = 1.f - wy;
        float r[4];
#pragma unroll
        for (int j = 0; j < 4; ++j) {
            int x = xb + j;
            int x0 = sy0[x], x1 = sy1[x];
            float wx = swy[x];
            float v00 = sr[y0 * 16 + x0], v01 = sr[y0 * 16 + x1];
            float v10 = sr[y1 * 16 + x0], v11 = sr[y1 * 16 + x1];
            float top = v00 * (1.f - wx) + v01 * wx;
            float bot = v10 * (1.f - wx) + v11 * wx;
            r[j] = top * cwy + bot * wy;
        }
        *(float4*)&ob[p] = make_float4(r[0], r[1], r[2], r[3]);
    }
}

// ============================ launch ===============================
extern "C" void kernel_launch(void* const* d_in, const int* in_sizes, int n_in,
                              void* d_out, int out_size) {
    const float* feat[5];
    for (int i = 0; i < 5; ++i) feat[i] = (const float*)d_in[i];
    const float* att = (const float*)d_in[5];
    const float* cw  = (const float*)d_in[18];
    float* out = (float*)d_out;

    static const int lgs[5]    = {6, 5, 4, 3, 2};
    static const int toffs[5]  = {0, 64, 96, 112, 120};
    static const int attoff[5] = {2793472, 44736512, 55222272, 57843712, 58499072};

    FeatPtrs fp;
    for (int i = 0; i < 5; ++i) fp.p[i] = feat[i];

    k_prep<<<12486, 256>>>(fp,
        (const float*)d_in[6],  (const float*)d_in[7],
        (const float*)d_in[8],  (const float*)d_in[9],
        (const float*)d_in[10], (const float*)d_in[11],
        (const float*)d_in[12], (const float*)d_in[13],
        (const float*)d_in[14], (const float*)d_in[15],
        (const float*)d_in[16], (const float*)d_in[17],
        cw, (const float*)d_in[19]);
    conv16<<<dim3(30, 10, 2), 256>>>(att);
    reduce_all<<<4800, 256>>>();
    k_logits<<<dim3(40, 4, 10), 256>>>();
    softmax_k<<<6400, 256>>>();
    k_vt<<<dim3(4, 100), 256>>>();
    vt_reduce<<<1280, 256>>>();
    k_h<<<dim3(2, 4, 10), 256>>>();
    k_part1<<<dim3(2, 86, 2), 256>>>(cw, fp, out);
    for (int l = 0; l < 5; ++l)
        attn_k<<<dim3(256, 40), 256>>>(out + attoff[l], l, lgs[l], toffs[l]);
}